// round 11
// baseline (speedup 1.0000x reference)
#include <cuda_runtime.h>
#include <cuda_bf16.h>
#include <cstdint>
#include <math.h>

// ---------------------------------------------------------------------------
// MultiLevelSimCLR, symmetric tiles, 4-warp 64x64 HMMA, N-halved software
// pipelining (MMA of half1 overlapped with epilogue of half0), 1 sync/tile.
// ---------------------------------------------------------------------------

#define B_INS   8192
#define N_INS   16384
#define DDIM    128
#define NPROW   131072
#define L2E10   14.4269504088896340f
#define NI_CTAS 688

// ---- static device scratch ----
__device__ __align__(16) uint32_t g_I[N_INS * 64];       // bf16 instance embs [r][128]
__device__ __align__(16) uint32_t g_P[NPROW * 64];       // bf16 patch embs
__device__ float g_part[128 * 128 * 128];                // [bi][bj][m]  8.4 MB
__device__ float g_pp[256 * 16 * 128];                   // [b][i*4+j][m] 2.1 MB
__device__ float g_fin1[512];
__device__ float g_fin2[1024];

__device__ __forceinline__ float ex2f(float x) {
    float y; asm("ex2.approx.f32 %0, %1;" : "=f"(y) : "f"(x)); return y;
}
__device__ __forceinline__ uint32_t smem_u32(const void* p) {
    uint32_t a;
    asm("{ .reg .u64 t; cvta.to.shared.u64 t, %1; cvt.u32.u64 %0, t; }" : "=r"(a) : "l"(p));
    return a;
}
__device__ __forceinline__ void mma16816(float* c, const uint32_t* a, uint32_t b0, uint32_t b1) {
    asm volatile(
        "mma.sync.aligned.m16n8k16.row.col.f32.bf16.bf16.f32 "
        "{%0,%1,%2,%3}, {%4,%5,%6,%7}, {%8,%9}, {%0,%1,%2,%3};"
        : "+f"(c[0]), "+f"(c[1]), "+f"(c[2]), "+f"(c[3])
        : "r"(a[0]), "r"(a[1]), "r"(a[2]), "r"(a[3]), "r"(b0), "r"(b1));
}
__device__ __forceinline__ void ldsm_x4(uint32_t* r, uint32_t addr) {
    asm volatile("ldmatrix.sync.aligned.m8n8.x4.shared.b16 {%0,%1,%2,%3}, [%4];"
        : "=r"(r[0]), "=r"(r[1]), "=r"(r[2]), "=r"(r[3]) : "r"(addr));
}
#define CP_ASYNC16(dst, src) asm volatile("cp.async.cg.shared.global [%0], [%1], 16;" :: "r"(dst), "l"(src))
#define CP_COMMIT()  asm volatile("cp.async.commit_group;" ::: "memory")
#define CP_WAIT0()   asm volatile("cp.async.wait_group 0;" ::: "memory")

// SMEM: A @0 (32KB), B0 @32768, B1 @65536, red[2] @98304 (2 x 2048B)
#define SM_A    0u
#define SM_B0   32768u
#define SM_RED  98304
#define SM_DYN  (98304 + 4096)

// copy a 128x128 bf16 tile global->smem, chunk-swizzled (128 threads)
__device__ __forceinline__ void cpa_tile(uint32_t dst, const char* __restrict__ src) {
    int tid = threadIdx.x;
#pragma unroll
    for (int i = 0; i < 16; i++) {
        int c = tid + i * 128;
        int r = c >> 4, cc = c & 15;
        uint32_t d = dst + r * 256 + (((uint32_t)(cc ^ (r & 7))) << 4);
        CP_ASYNC16(d, src + r * 256 + cc * 16);
    }
}

// ---------------------------------------------------------------------------
// Prep kernels
// ---------------------------------------------------------------------------
__global__ void prep_ins(const float* __restrict__ v1, const float* __restrict__ v2) {
    int lane = threadIdx.x & 31;
    int gw = (blockIdx.x * blockDim.x + threadIdx.x) >> 5;
    for (int r = gw; r < N_INS; r += 4096) {
        const float* src = (r < B_INS) ? v1 + (size_t)r * DDIM : v2 + (size_t)(r - B_INS) * DDIM;
        float4 x = ((const float4*)src)[lane];
        float ss = x.x * x.x + x.y * x.y + x.z * x.z + x.w * x.w;
#pragma unroll
        for (int o = 16; o; o >>= 1) ss += __shfl_xor_sync(~0u, ss, o);
        float ri = 1.0f / fmaxf(sqrtf(ss), 1e-12f);
        __nv_bfloat162 p0 = __floats2bfloat162_rn(x.x * ri, x.y * ri);
        __nv_bfloat162 p1 = __floats2bfloat162_rn(x.z * ri, x.w * ri);
        ((uint2*)g_I)[(size_t)r * 32 + lane] = make_uint2(*(uint32_t*)&p0, *(uint32_t*)&p1);
    }
}

__global__ void prep_patch(const float* __restrict__ v1p, const float* __restrict__ v2p) {
    __shared__ float sb[2][32][129];
    int tid = threadIdx.x, lane = tid & 31, wid = tid >> 5;
    int j0 = blockIdx.x * 32;
    int b = blockIdx.y;
    const float* srcs[2] = { v1p + (size_t)b * DDIM * 256, v2p + (size_t)b * DDIM * 256 };
#pragma unroll
    for (int s = 0; s < 2; s++) {
        const float* src = srcs[s];
        for (int i = 0; i < 16; i++) {
            int idx = tid + i * 256;
            int k = idx >> 5, jj = idx & 31;
            sb[s][jj][k] = src[(size_t)k * 256 + j0 + jj];
        }
    }
    __syncthreads();
    for (int t = 0; t < 8; t++) {
        int rr = wid * 8 + t;
        int s = rr >> 5, jj = rr & 31;
        float x0 = sb[s][jj][lane * 4 + 0];
        float x1 = sb[s][jj][lane * 4 + 1];
        float x2 = sb[s][jj][lane * 4 + 2];
        float x3 = sb[s][jj][lane * 4 + 3];
        float ss = x0 * x0 + x1 * x1 + x2 * x2 + x3 * x3;
#pragma unroll
        for (int o = 16; o; o >>= 1) ss += __shfl_xor_sync(~0u, ss, o);
        float ri = 1.0f / fmaxf(sqrtf(ss), 1e-12f);
        __nv_bfloat162 p0 = __floats2bfloat162_rn(x0 * ri, x1 * ri);
        __nv_bfloat162 p1 = __floats2bfloat162_rn(x2 * ri, x3 * ri);
        size_t row = (size_t)b * 512 + s * 256 + j0 + jj;
        ((uint2*)g_P)[row * 32 + lane] = make_uint2(*(uint32_t*)&p0, *(uint32_t*)&p1);
    }
}

// epilogue micro-op: e = exp(10d-10), accumulate row + col sums
#define EPI1(ACC, MI, S, Q, CS)                                          \
    {                                                                    \
        float e = ex2f(fmaf(ACC[MI][S][Q], L2E10, -L2E10));              \
        rsum[MI][(Q) >> 1] += e;                                         \
        CS[(S) * 2 + ((Q) & 1)] += e;                                    \
    }

// ---------------------------------------------------------------------------
// Main kernel: 128 threads, 4 warps as 2(M) x 2(N), 64x64 per warp,
// split into two 64x32 halves with interleaved MMA/epilogue.
// ---------------------------------------------------------------------------
__global__ void __launch_bounds__(128, 2) k_main() {
    extern __shared__ char sm[];
    uint32_t sbu = smem_u32(sm);

    int tid = threadIdx.x, lane = tid & 31, wid = tid >> 5;
    int g = lane >> 2, t = lane & 3;
    int l7 = lane & 7, l15 = lane & 15, hi = lane >> 4;
    int warpM = wid >> 1, warpN = wid & 1;
    int woff = warpM * 64, noff = warpN * 64;

    int bid = blockIdx.x;
    const char* Asrc;
    const char* Bembs;
    float* partBase;
    int pairStrideRow;
    int rowIdx;
    int bj0, bjstep, L;

    if (bid < NI_CTAS) {
        int x, slot, ns;
        if (bid < 512)      { x = bid >> 3;               slot = bid & 7;         ns = 8; }
        else if (bid < 640) { x = 64 + ((bid - 512) >> 2); slot = (bid - 512) & 3; ns = 4; }
        else if (bid < 672) { x = 96 + ((bid - 640) >> 1); slot = (bid - 640) & 1; ns = 2; }
        else                { x = 112 + (bid - 672);       slot = 0;               ns = 1; }
        rowIdx = x;
        bj0 = x + slot; bjstep = ns;
        L = (bj0 <= 127) ? ((127 - bj0) / ns) + 1 : 0;
        Asrc = (const char*)g_I + (size_t)x * 32768;
        Bembs = (const char*)g_I;
        partBase = g_part;
        pairStrideRow = 128;
    } else {
        int pc = bid - NI_CTAS;
        int b = pc >> 2, bi = pc & 3;
        rowIdx = bi;
        bj0 = bi; bjstep = 1;
        L = 4 - bi;
        Asrc = (const char*)g_P + ((size_t)b * 512 + (size_t)bi * 128) * 256;
        Bembs = (const char*)g_P + (size_t)b * 512 * 256;
        partBase = g_pp + (size_t)b * 16 * 128;
        pairStrideRow = 4;
    }
    if (L <= 0) return;

    // prologue: A + B0 in one group
    cpa_tile(sbu + SM_A, Asrc);
    cpa_tile(sbu + SM_B0, Bembs + (size_t)bj0 * 32768);
    CP_COMMIT();

    uint32_t aAddr = sbu + SM_A + (uint32_t)(woff + l15) * 256;
    uint32_t bRowOff = (uint32_t)(noff + l15) * 256;

    float* outRprev = 0;
    float* outCprev = 0;
    bool diagprev = false;

    for (int i = 0; i < L; i++) {
        int bj = bj0 + i * bjstep;
        bool diag = (bj == rowIdx);

        CP_WAIT0();
        __syncthreads();

        // flush previous tile's reduced partials
        if (i > 0) {
            float* rr = (float*)(sm + SM_RED + ((i - 1) & 1) * 2048);
            outRprev[tid] = rr[tid] + rr[128 + tid];
            if (!diagprev) outCprev[tid] = rr[256 + tid] + rr[384 + tid];
        }

        // prefetch next tile into the buffer freed by tile i-1
        if (i + 1 < L) {
            cpa_tile(sbu + SM_B0 + ((uint32_t)((i + 1) & 1) << 15),
                     Bembs + (size_t)(bj + bjstep) * 32768);
            CP_COMMIT();
        }

        uint32_t bbuf = sbu + SM_B0 + ((uint32_t)(i & 1) << 15);
        uint32_t bRow = bbuf + bRowOff;

        float rsum[4][2];
        float csum0[8], csum1[8];
#pragma unroll
        for (int mi = 0; mi < 4; mi++) { rsum[mi][0] = 0.f; rsum[mi][1] = 0.f; }
#pragma unroll
        for (int k2 = 0; k2 < 8; k2++) { csum0[k2] = 0.f; csum1[k2] = 0.f; }

        float acc0[4][4][4], acc1[4][4][4];
#pragma unroll
        for (int mi = 0; mi < 4; mi++)
#pragma unroll
            for (int s = 0; s < 4; s++)
#pragma unroll
                for (int q = 0; q < 4; q++) { acc0[mi][s][q] = 0.f; acc1[mi][s][q] = 0.f; }

        // ---- half 0 MMA (cols noff+0..31) ----
#pragma unroll
        for (int ks = 0; ks < 8; ks++) {
            uint32_t coff = (uint32_t)((((ks << 1) | hi) ^ l7) << 4);
            uint32_t a[4][4];
#pragma unroll
            for (int mi = 0; mi < 4; mi++)
                ldsm_x4(a[mi], aAddr + mi * 16 * 256 + coff);
            uint32_t b0[4], b1[4];
            ldsm_x4(b0, bRow + 0 * 16 * 256 + coff);
            ldsm_x4(b1, bRow + 1 * 16 * 256 + coff);
#pragma unroll
            for (int mi = 0; mi < 4; mi++) {
                mma16816(acc0[mi][0], a[mi], b0[0], b0[2]);
                mma16816(acc0[mi][1], a[mi], b0[1], b0[3]);
                mma16816(acc0[mi][2], a[mi], b1[0], b1[2]);
                mma16816(acc0[mi][3], a[mi], b1[1], b1[3]);
            }
        }

        // ---- half 1 MMA (cols noff+32..63) interleaved with epilogue(half 0) ----
#pragma unroll
        for (int ks = 0; ks < 8; ks++) {
            uint32_t coff = (uint32_t)((((ks << 1) | hi) ^ l7) << 4);
            uint32_t a[4][4];
#pragma unroll
            for (int mi = 0; mi < 4; mi++)
                ldsm_x4(a[mi], aAddr + mi * 16 * 256 + coff);
            uint32_t b0[4], b1[4];
            ldsm_x4(b0, bRow + 2 * 16 * 256 + coff);
            ldsm_x4(b1, bRow + 3 * 16 * 256 + coff);

            int emi = ks >> 1, es = (ks & 1) * 2;
#pragma unroll
            for (int mi = 0; mi < 4; mi++) {
                mma16816(acc1[mi][0], a[mi], b0[0], b0[2]);
                mma16816(acc1[mi][1], a[mi], b0[1], b0[3]);
                // interleave 4 epilogue values of half 0
                if (mi == 0) { EPI1(acc0, emi, es, 0, csum0); EPI1(acc0, emi, es, 1, csum0); }
                if (mi == 1) { EPI1(acc0, emi, es, 2, csum0); EPI1(acc0, emi, es, 3, csum0); }
                mma16816(acc1[mi][2], a[mi], b1[0], b1[2]);
                mma16816(acc1[mi][3], a[mi], b1[1], b1[3]);
                if (mi == 2) { EPI1(acc0, emi, es + 1, 0, csum0); EPI1(acc0, emi, es + 1, 1, csum0); }
                if (mi == 3) { EPI1(acc0, emi, es + 1, 2, csum0); EPI1(acc0, emi, es + 1, 3, csum0); }
            }
        }

        // ---- tail epilogue (half 1) ----
#pragma unroll
        for (int mi = 0; mi < 4; mi++)
#pragma unroll
            for (int s = 0; s < 4; s++)
#pragma unroll
                for (int q = 0; q < 4; q++) EPI1(acc1, mi, s, q, csum1);

        // reductions into red[i&1]
        float* red = (float*)(sm + SM_RED + (i & 1) * 2048);
#pragma unroll
        for (int mi = 0; mi < 4; mi++)
#pragma unroll
            for (int h = 0; h < 2; h++) {
                float v = rsum[mi][h];
                v += __shfl_xor_sync(~0u, v, 1);
                v += __shfl_xor_sync(~0u, v, 2);
                if (t == 0) red[warpN * 128 + woff + mi * 16 + h * 8 + g] = v;
            }
#pragma unroll
        for (int h = 0; h < 2; h++) {
            float* cs = h ? csum1 : csum0;
#pragma unroll
            for (int k2 = 0; k2 < 8; k2++) {
                float v = cs[k2];
                v += __shfl_xor_sync(~0u, v, 4);
                v += __shfl_xor_sync(~0u, v, 8);
                v += __shfl_xor_sync(~0u, v, 16);
                if (g == 0)
                    red[256 + warpM * 128 + noff + h * 32 + (k2 >> 1) * 8 + t * 2 + (k2 & 1)] = v;
            }
        }

        outRprev = partBase + (size_t)(rowIdx * pairStrideRow + bj) * 128;
        outCprev = partBase + (size_t)(bj * pairStrideRow + rowIdx) * 128;
        diagprev = diag;
    }

    __syncthreads();
    {
        float* rr = (float*)(sm + SM_RED + ((L - 1) & 1) * 2048);
        outRprev[tid] = rr[tid] + rr[128 + tid];
        if (!diagprev) outCprev[tid] = rr[256 + tid] + rr[384 + tid];
    }
}

// ---------------------------------------------------------------------------
// Fixups
// ---------------------------------------------------------------------------
__device__ __forceinline__ void dots_row(const uint2* a, const uint2* b, int lane,
                                         float& pos, float& dia) {
    uint2 ua = a[lane], ub = b[lane];
    __nv_bfloat162 a0 = *(__nv_bfloat162*)&ua.x, a1 = *(__nv_bfloat162*)&ua.y;
    __nv_bfloat162 b0 = *(__nv_bfloat162*)&ub.x, b1 = *(__nv_bfloat162*)&ub.y;
    float ax0 = __bfloat162float(a0.x), ax1 = __bfloat162float(a0.y);
    float ax2 = __bfloat162float(a1.x), ax3 = __bfloat162float(a1.y);
    float bx0 = __bfloat162float(b0.x), bx1 = __bfloat162float(b0.y);
    float bx2 = __bfloat162float(b1.x), bx3 = __bfloat162float(b1.y);
    pos = ax0 * bx0 + ax1 * bx1 + ax2 * bx2 + ax3 * bx3;
    dia = ax0 * ax0 + ax1 * ax1 + ax2 * ax2 + ax3 * ax3;
#pragma unroll
    for (int o = 16; o; o >>= 1) {
        pos += __shfl_xor_sync(~0u, pos, o);
        dia += __shfl_xor_sync(~0u, dia, o);
    }
}

// grid 512: (bi = blk>>2, quarter q = blk&3)
__global__ void fin_ins() {
    __shared__ float S2[8][32];
    __shared__ float S[32];
    __shared__ float rs[8];
    int bi = blockIdx.x >> 2, q = blockIdx.x & 3;
    int tid = threadIdx.x;
    int m = tid & 31, jg = tid >> 5;

    const float* base = g_part + (size_t)bi * 128 * 128 + q * 32 + m;
    float s = 0.0f;
#pragma unroll
    for (int j = jg * 16; j < jg * 16 + 16; j++) s += base[(size_t)j * 128];
    S2[jg][m] = s;
    __syncthreads();
    if (tid < 32) {
        float v = 0.0f;
#pragma unroll
        for (int j = 0; j < 8; j++) v += S2[j][tid];
        S[tid] = v;
    }
    __syncthreads();

    int lane = tid & 31, wid = tid >> 5;
    float acc = 0.0f;
#pragma unroll
    for (int ii = 0; ii < 4; ii++) {
        int mm = wid * 4 + ii;
        int r = bi * 128 + q * 32 + mm;
        float pos, dia;
        dots_row(((const uint2*)g_I) + (size_t)r * 32,
                 ((const uint2*)g_I) + (size_t)(r ^ B_INS) * 32, lane, pos, dia);
        if (lane == 0) {
            float Sv = S[mm] - ex2f(fmaf(dia, L2E10, -L2E10));
            acc += 10.0f + logf(Sv) - 10.0f * pos;
        }
    }
    if (lane == 0) rs[wid] = acc;
    __syncthreads();
    if (tid == 0) {
        float v = 0.0f;
#pragma unroll
        for (int i = 0; i < 8; i++) v += rs[i];
        g_fin1[blockIdx.x] = v;
    }
}

__global__ void fin_patch(const int* __restrict__ c1, const int* __restrict__ c2) {
    __shared__ float S2[256];
    __shared__ float S[128];
    __shared__ float rs[256];
    int pc = blockIdx.x;
    int b = pc >> 2, bi = pc & 3;
    int tid = threadIdx.x;
    int m = tid & 127, jh = tid >> 7;

    const float* base = g_pp + ((size_t)b * 16 + bi * 4) * 128 + m;
    float s = 0.0f;
#pragma unroll
    for (int j = jh * 2; j < jh * 2 + 2; j++) s += base[(size_t)j * 128];
    S2[tid] = s;
    __syncthreads();
    if (tid < 128) S[tid] = S2[tid] + S2[tid + 128];
    __syncthreads();

    int lane = tid & 31, wid = tid >> 5;
    float acc = 0.0f;
#pragma unroll 4
    for (int ii = 0; ii < 16; ii++) {
        int mm = wid * 16 + ii;
        int rl = bi * 128 + mm;
        int r = b * 512 + rl;
        int c = (rl < 256) ? c1[b * 256 + rl] : c2[b * 256 + rl - 256];
        float pos, dia;
        dots_row(((const uint2*)g_P) + (size_t)r * 32,
                 ((const uint2*)g_P) + (size_t)(r ^ 256) * 32, lane, pos, dia);
        if (lane == 0 && c != 0) {
            float Sv = S[mm] - ex2f(fmaf(dia, L2E10, -L2E10));
            acc += 10.0f + logf(Sv) - 10.0f * pos;
        }
    }
    rs[tid] = acc;
    __syncthreads();
    for (int s2 = 128; s2; s2 >>= 1) { if (tid < s2) rs[tid] += rs[tid + s2]; __syncthreads(); }
    if (tid == 0) g_fin2[pc] = rs[0];
}

__global__ void k_combine(const int* __restrict__ c1, const int* __restrict__ c2,
                          float* __restrict__ out) {
    __shared__ float rs[256];
    __shared__ int ri[256];
    int tid = threadIdx.x;
    float a = g_fin1[tid] + g_fin1[tid + 256];
    float p = 0.0f;
    int cnt = 0;
    for (int i = tid; i < 1024; i += 256) p += g_fin2[i];
    for (int i = tid; i < 65536; i += 256) cnt += (c1[i] != 0) + (c2[i] != 0);
    rs[tid] = a; ri[tid] = cnt;
    __syncthreads();
    for (int s = 128; s; s >>= 1) {
        if (tid < s) { rs[tid] += rs[tid + s]; ri[tid] += ri[tid + s]; }
        __syncthreads();
    }
    float ins_sum = rs[0];
    int nvalid = ri[0];
    __syncthreads();
    rs[tid] = p;
    __syncthreads();
    for (int s = 128; s; s >>= 1) { if (tid < s) rs[tid] += rs[tid + s]; __syncthreads(); }
    if (tid == 0)
        out[0] = ins_sum / (float)N_INS + rs[0] / (float)nvalid;
}

// ---------------------------------------------------------------------------
extern "C" void kernel_launch(void* const* d_in, const int* in_sizes, int n_in,
                              void* d_out, int out_size) {
    const float* v1  = (const float*)d_in[0];
    const float* v2  = (const float*)d_in[1];
    const float* v1p = (const float*)d_in[2];
    const float* v2p = (const float*)d_in[3];
    const int*   c1  = (const int*)d_in[4];
    const int*   c2  = (const int*)d_in[5];
    float* out = (float*)d_out;

    cudaFuncSetAttribute(k_main, cudaFuncAttributeMaxDynamicSharedMemorySize, SM_DYN);

    prep_ins<<<512, 256>>>(v1, v2);
    prep_patch<<<dim3(8, 256), 256>>>(v1p, v2p);
    k_main<<<NI_CTAS + 1024, 128, SM_DYN>>>();
    fin_ins<<<512, 256>>>();
    fin_patch<<<1024, 256>>>(c1, c2);
    k_combine<<<1, 256>>>(c1, c2, out);
}

// round 12
// speedup vs baseline: 1.0583x; 1.0583x over previous
#include <cuda_runtime.h>
#include <cuda_bf16.h>
#include <cstdint>
#include <math.h>

// ---------------------------------------------------------------------------
// MultiLevelSimCLR, symmetric tiles, 4-warp 64x64-tile HMMA, occ-2,
// single-sync pipelined tiles, fused prep/fin stages.
// ---------------------------------------------------------------------------

#define B_INS   8192
#define N_INS   16384
#define DDIM    128
#define NPROW   131072
#define L2E10   14.4269504088896340f
#define NI_CTAS 688

// ---- static device scratch ----
__device__ __align__(16) uint32_t g_I[N_INS * 64];       // bf16 instance embs [r][128]
__device__ __align__(16) uint32_t g_P[NPROW * 64];       // bf16 patch embs
__device__ float g_part[128 * 128 * 128];                // [bi][bj][m]  8.4 MB
__device__ float g_pp[256 * 16 * 128];                   // [b][i*4+j][m] 2.1 MB
__device__ float g_fin1[512];
__device__ float g_fin2[1024];

__device__ __forceinline__ float ex2f(float x) {
    float y; asm("ex2.approx.f32 %0, %1;" : "=f"(y) : "f"(x)); return y;
}
__device__ __forceinline__ uint32_t smem_u32(const void* p) {
    uint32_t a;
    asm("{ .reg .u64 t; cvta.to.shared.u64 t, %1; cvt.u32.u64 %0, t; }" : "=r"(a) : "l"(p));
    return a;
}
__device__ __forceinline__ void mma16816(float* c, const uint32_t* a, uint32_t b0, uint32_t b1) {
    asm volatile(
        "mma.sync.aligned.m16n8k16.row.col.f32.bf16.bf16.f32 "
        "{%0,%1,%2,%3}, {%4,%5,%6,%7}, {%8,%9}, {%0,%1,%2,%3};"
        : "+f"(c[0]), "+f"(c[1]), "+f"(c[2]), "+f"(c[3])
        : "r"(a[0]), "r"(a[1]), "r"(a[2]), "r"(a[3]), "r"(b0), "r"(b1));
}
__device__ __forceinline__ void ldsm_x4(uint32_t* r, uint32_t addr) {
    asm volatile("ldmatrix.sync.aligned.m8n8.x4.shared.b16 {%0,%1,%2,%3}, [%4];"
        : "=r"(r[0]), "=r"(r[1]), "=r"(r[2]), "=r"(r[3]) : "r"(addr));
}
#define CP_ASYNC16(dst, src) asm volatile("cp.async.cg.shared.global [%0], [%1], 16;" :: "r"(dst), "l"(src))
#define CP_COMMIT()  asm volatile("cp.async.commit_group;" ::: "memory")
#define CP_WAIT0()   asm volatile("cp.async.wait_group 0;" ::: "memory")

// SMEM: A @0 (32KB), B0 @32768, B1 @65536, red[2] @98304 (2 x 2048B)
#define SM_A    0u
#define SM_B0   32768u
#define SM_RED  98304
#define SM_DYN  (98304 + 4096)

// copy a 128x128 bf16 tile global->smem, chunk-swizzled (128 threads)
__device__ __forceinline__ void cpa_tile(uint32_t dst, const char* __restrict__ src) {
    int tid = threadIdx.x;
#pragma unroll
    for (int i = 0; i < 16; i++) {
        int c = tid + i * 128;
        int r = c >> 4, cc = c & 15;
        uint32_t d = dst + r * 256 + (((uint32_t)(cc ^ (r & 7))) << 4);
        CP_ASYNC16(d, src + r * 256 + cc * 16);
    }
}

// ---------------------------------------------------------------------------
// Fused prep: blocks 0..511 instance, 512..2559 patch.
// ---------------------------------------------------------------------------
__global__ void prep_all(const float* __restrict__ v1, const float* __restrict__ v2,
                         const float* __restrict__ v1p, const float* __restrict__ v2p) {
    __shared__ float sb[2][32][129];
    int tid = threadIdx.x, lane = tid & 31, wid = tid >> 5;

    if (blockIdx.x < 512) {
        int gw = (blockIdx.x * 256 + tid) >> 5;
        for (int r = gw; r < N_INS; r += 4096) {
            const float* src = (r < B_INS) ? v1 + (size_t)r * DDIM : v2 + (size_t)(r - B_INS) * DDIM;
            float4 x = ((const float4*)src)[lane];
            float ss = x.x * x.x + x.y * x.y + x.z * x.z + x.w * x.w;
#pragma unroll
            for (int o = 16; o; o >>= 1) ss += __shfl_xor_sync(~0u, ss, o);
            float ri = 1.0f / fmaxf(sqrtf(ss), 1e-12f);
            __nv_bfloat162 p0 = __floats2bfloat162_rn(x.x * ri, x.y * ri);
            __nv_bfloat162 p1 = __floats2bfloat162_rn(x.z * ri, x.w * ri);
            ((uint2*)g_I)[(size_t)r * 32 + lane] = make_uint2(*(uint32_t*)&p0, *(uint32_t*)&p1);
        }
        return;
    }

    int pc = blockIdx.x - 512;
    int j0 = (pc & 7) * 32;
    int b = pc >> 3;
    const float* srcs[2] = { v1p + (size_t)b * DDIM * 256, v2p + (size_t)b * DDIM * 256 };
#pragma unroll
    for (int s = 0; s < 2; s++) {
        const float* src = srcs[s];
        for (int i = 0; i < 16; i++) {
            int idx = tid + i * 256;
            int k = idx >> 5, jj = idx & 31;
            sb[s][jj][k] = src[(size_t)k * 256 + j0 + jj];
        }
    }
    __syncthreads();
    for (int t = 0; t < 8; t++) {
        int rr = wid * 8 + t;
        int s = rr >> 5, jj = rr & 31;
        float x0 = sb[s][jj][lane * 4 + 0];
        float x1 = sb[s][jj][lane * 4 + 1];
        float x2 = sb[s][jj][lane * 4 + 2];
        float x3 = sb[s][jj][lane * 4 + 3];
        float ss = x0 * x0 + x1 * x1 + x2 * x2 + x3 * x3;
#pragma unroll
        for (int o = 16; o; o >>= 1) ss += __shfl_xor_sync(~0u, ss, o);
        float ri = 1.0f / fmaxf(sqrtf(ss), 1e-12f);
        __nv_bfloat162 p0 = __floats2bfloat162_rn(x0 * ri, x1 * ri);
        __nv_bfloat162 p1 = __floats2bfloat162_rn(x2 * ri, x3 * ri);
        size_t row = (size_t)b * 512 + s * 256 + j0 + jj;
        ((uint2*)g_P)[row * 32 + lane] = make_uint2(*(uint32_t*)&p0, *(uint32_t*)&p1);
    }
}

// ---------------------------------------------------------------------------
// Main kernel: 128 threads, 4 warps as 2(M) x 2(N), 64x64 per warp.
// One __syncthreads per tile; prefetch(i+1) issued at tile top.
// ---------------------------------------------------------------------------
__global__ void __launch_bounds__(128, 2) k_main() {
    extern __shared__ char sm[];
    uint32_t sbu = smem_u32(sm);

    int tid = threadIdx.x, lane = tid & 31, wid = tid >> 5;
    int g = lane >> 2, t = lane & 3;
    int l7 = lane & 7, l15 = lane & 15, hi = lane >> 4;
    int warpM = wid >> 1, warpN = wid & 1;
    int woff = warpM * 64, noff = warpN * 64;

    int bid = blockIdx.x;
    const char* Asrc;
    const char* Bembs;
    float* partBase;
    int pairStrideRow;
    int rowIdx;
    int bj0, bjstep, L;

    if (bid < NI_CTAS) {
        int x, slot, ns;
        if (bid < 512)      { x = bid >> 3;               slot = bid & 7;         ns = 8; }
        else if (bid < 640) { x = 64 + ((bid - 512) >> 2); slot = (bid - 512) & 3; ns = 4; }
        else if (bid < 672) { x = 96 + ((bid - 640) >> 1); slot = (bid - 640) & 1; ns = 2; }
        else                { x = 112 + (bid - 672);       slot = 0;               ns = 1; }
        rowIdx = x;
        bj0 = x + slot; bjstep = ns;
        L = (bj0 <= 127) ? ((127 - bj0) / ns) + 1 : 0;
        Asrc = (const char*)g_I + (size_t)x * 32768;
        Bembs = (const char*)g_I;
        partBase = g_part;
        pairStrideRow = 128;
    } else {
        int pc = bid - NI_CTAS;
        int b = pc >> 2, bi = pc & 3;
        rowIdx = bi;
        bj0 = bi; bjstep = 1;
        L = 4 - bi;
        Asrc = (const char*)g_P + ((size_t)b * 512 + (size_t)bi * 128) * 256;
        Bembs = (const char*)g_P + (size_t)b * 512 * 256;
        partBase = g_pp + (size_t)b * 16 * 128;
        pairStrideRow = 4;
    }
    if (L <= 0) return;

    // prologue: A + B0 in one group
    cpa_tile(sbu + SM_A, Asrc);
    cpa_tile(sbu + SM_B0, Bembs + (size_t)bj0 * 32768);
    CP_COMMIT();

    uint32_t aAddr = sbu + SM_A + (uint32_t)(woff + l15) * 256;
    uint32_t bRowOff = (uint32_t)(noff + l15) * 256;

    float* outRprev = 0;
    float* outCprev = 0;
    bool diagprev = false;

    for (int i = 0; i < L; i++) {
        int bj = bj0 + i * bjstep;
        bool diag = (bj == rowIdx);

        CP_WAIT0();
        __syncthreads();

        // flush previous tile's reduced partials (red[(i-1)&1])
        if (i > 0) {
            float* rr = (float*)(sm + SM_RED + ((i - 1) & 1) * 2048);
            outRprev[tid] = rr[tid] + rr[128 + tid];
            if (!diagprev) outCprev[tid] = rr[256 + tid] + rr[384 + tid];
        }

        // prefetch tile i+1 into the buffer tile i-1 used (readers passed sync)
        if (i + 1 < L) {
            cpa_tile(sbu + SM_B0 + ((uint32_t)((i + 1) & 1) << 15),
                     Bembs + (size_t)(bj + bjstep) * 32768);
            CP_COMMIT();
        }

        uint32_t bbuf = sbu + SM_B0 + ((uint32_t)(i & 1) << 15);
        uint32_t bRow = bbuf + bRowOff;

        float acc[4][8][4];
#pragma unroll
        for (int mi = 0; mi < 4; mi++)
#pragma unroll
            for (int ni = 0; ni < 8; ni++)
#pragma unroll
                for (int q = 0; q < 4; q++) acc[mi][ni][q] = 0.f;

#pragma unroll
        for (int ks = 0; ks < 8; ks++) {
            uint32_t coff = (uint32_t)((((ks << 1) | hi) ^ l7) << 4);
            uint32_t a[4][4];
#pragma unroll
            for (int mi = 0; mi < 4; mi++)
                ldsm_x4(a[mi], aAddr + mi * 16 * 256 + coff);
            uint32_t b[4][4];
#pragma unroll
            for (int nj = 0; nj < 4; nj++)
                ldsm_x4(b[nj], bRow + nj * 16 * 256 + coff);
#pragma unroll
            for (int nj = 0; nj < 4; nj++)
#pragma unroll
                for (int mi = 0; mi < 4; mi++) {
                    mma16816(acc[mi][nj * 2 + 0], a[mi], b[nj][0], b[nj][2]);
                    mma16816(acc[mi][nj * 2 + 1], a[mi], b[nj][1], b[nj][3]);
                }
        }

        // epilogue: e = exp(10d - 10); row + col sums into red[i&1]
        float rsum[4][2];
        float csum[16];
#pragma unroll
        for (int mi = 0; mi < 4; mi++) { rsum[mi][0] = 0.f; rsum[mi][1] = 0.f; }
#pragma unroll
        for (int k2 = 0; k2 < 16; k2++) csum[k2] = 0.f;

#pragma unroll
        for (int mi = 0; mi < 4; mi++)
#pragma unroll
            for (int ni = 0; ni < 8; ni++)
#pragma unroll
                for (int q = 0; q < 4; q++) {
                    float e = ex2f(fmaf(acc[mi][ni][q], L2E10, -L2E10));
                    rsum[mi][q >> 1] += e;
                    csum[ni * 2 + (q & 1)] += e;
                }

        float* red = (float*)(sm + SM_RED + (i & 1) * 2048);
#pragma unroll
        for (int mi = 0; mi < 4; mi++)
#pragma unroll
            for (int h = 0; h < 2; h++) {
                float v = rsum[mi][h];
                v += __shfl_xor_sync(~0u, v, 1);
                v += __shfl_xor_sync(~0u, v, 2);
                if (t == 0) red[warpN * 128 + woff + mi * 16 + h * 8 + g] = v;
            }
#pragma unroll
        for (int k2 = 0; k2 < 16; k2++) {
            float v = csum[k2];
            v += __shfl_xor_sync(~0u, v, 4);
            v += __shfl_xor_sync(~0u, v, 8);
            v += __shfl_xor_sync(~0u, v, 16);
            if (g == 0) red[256 + warpM * 128 + noff + (k2 >> 1) * 8 + t * 2 + (k2 & 1)] = v;
        }

        outRprev = partBase + (size_t)(rowIdx * pairStrideRow + bj) * 128;
        outCprev = partBase + (size_t)(bj * pairStrideRow + rowIdx) * 128;
        diagprev = diag;
    }

    __syncthreads();
    {
        float* rr = (float*)(sm + SM_RED + ((L - 1) & 1) * 2048);
        outRprev[tid] = rr[tid] + rr[128 + tid];
        if (!diagprev) outCprev[tid] = rr[256 + tid] + rr[384 + tid];
    }
}

// ---------------------------------------------------------------------------
// Fused fixup: blocks 0..511 instance quarters, 512..1535 patch.
// ---------------------------------------------------------------------------
__device__ __forceinline__ void dots_row(const uint2* a, const uint2* b, int lane,
                                         float& pos, float& dia) {
    uint2 ua = a[lane], ub = b[lane];
    __nv_bfloat162 a0 = *(__nv_bfloat162*)&ua.x, a1 = *(__nv_bfloat162*)&ua.y;
    __nv_bfloat162 b0 = *(__nv_bfloat162*)&ub.x, b1 = *(__nv_bfloat162*)&ub.y;
    float ax0 = __bfloat162float(a0.x), ax1 = __bfloat162float(a0.y);
    float ax2 = __bfloat162float(a1.x), ax3 = __bfloat162float(a1.y);
    float bx0 = __bfloat162float(b0.x), bx1 = __bfloat162float(b0.y);
    float bx2 = __bfloat162float(b1.x), bx3 = __bfloat162float(b1.y);
    pos = ax0 * bx0 + ax1 * bx1 + ax2 * bx2 + ax3 * bx3;
    dia = ax0 * ax0 + ax1 * ax1 + ax2 * ax2 + ax3 * ax3;
#pragma unroll
    for (int o = 16; o; o >>= 1) {
        pos += __shfl_xor_sync(~0u, pos, o);
        dia += __shfl_xor_sync(~0u, dia, o);
    }
}

__global__ void fin_all(const int* __restrict__ c1, const int* __restrict__ c2) {
    __shared__ float S2a[8][32];
    __shared__ float S2b[256];
    __shared__ float S[128];
    __shared__ float rs[256];
    int tid = threadIdx.x;
    int lane = tid & 31, wid = tid >> 5;

    if (blockIdx.x < 512) {
        int bi = blockIdx.x >> 2, q = blockIdx.x & 3;
        int m = tid & 31, jg = tid >> 5;

        const float* base = g_part + (size_t)bi * 128 * 128 + q * 32 + m;
        float s = 0.0f;
#pragma unroll
        for (int j = jg * 16; j < jg * 16 + 16; j++) s += base[(size_t)j * 128];
        S2a[jg][m] = s;
        __syncthreads();
        if (tid < 32) {
            float v = 0.0f;
#pragma unroll
            for (int j = 0; j < 8; j++) v += S2a[j][tid];
            S[tid] = v;
        }
        __syncthreads();

        float acc = 0.0f;
#pragma unroll
        for (int ii = 0; ii < 4; ii++) {
            int mm = wid * 4 + ii;
            int r = bi * 128 + q * 32 + mm;
            float pos, dia;
            dots_row(((const uint2*)g_I) + (size_t)r * 32,
                     ((const uint2*)g_I) + (size_t)(r ^ B_INS) * 32, lane, pos, dia);
            if (lane == 0) {
                float Sv = S[mm] - ex2f(fmaf(dia, L2E10, -L2E10));
                acc += 10.0f + logf(Sv) - 10.0f * pos;
            }
        }
        if (lane == 0) rs[wid] = acc;
        __syncthreads();
        if (tid == 0) {
            float v = 0.0f;
#pragma unroll
            for (int i = 0; i < 8; i++) v += rs[i];
            g_fin1[blockIdx.x] = v;
        }
        return;
    }

    int pc = blockIdx.x - 512;
    int b = pc >> 2, bi = pc & 3;
    int m = tid & 127, jh = tid >> 7;

    const float* base = g_pp + ((size_t)b * 16 + bi * 4) * 128 + m;
    float s = 0.0f;
#pragma unroll
    for (int j = jh * 2; j < jh * 2 + 2; j++) s += base[(size_t)j * 128];
    S2b[tid] = s;
    __syncthreads();
    if (tid < 128) S[tid] = S2b[tid] + S2b[tid + 128];
    __syncthreads();

    float acc = 0.0f;
#pragma unroll 4
    for (int ii = 0; ii < 16; ii++) {
        int mm = wid * 16 + ii;
        int rl = bi * 128 + mm;
        int r = b * 512 + rl;
        int c = (rl < 256) ? c1[b * 256 + rl] : c2[b * 256 + rl - 256];
        float pos, dia;
        dots_row(((const uint2*)g_P) + (size_t)r * 32,
                 ((const uint2*)g_P) + (size_t)(r ^ 256) * 32, lane, pos, dia);
        if (lane == 0 && c != 0) {
            float Sv = S[mm] - ex2f(fmaf(dia, L2E10, -L2E10));
            acc += 10.0f + logf(Sv) - 10.0f * pos;
        }
    }
    rs[tid] = acc;
    __syncthreads();
    for (int s2 = 128; s2; s2 >>= 1) { if (tid < s2) rs[tid] += rs[tid + s2]; __syncthreads(); }
    if (tid == 0) g_fin2[pc] = rs[0];
}

__global__ void k_combine(const int* __restrict__ c1, const int* __restrict__ c2,
                          float* __restrict__ out) {
    __shared__ float rs[256];
    __shared__ int ri[256];
    int tid = threadIdx.x;
    float a = g_fin1[tid] + g_fin1[tid + 256];
    float p = 0.0f;
    int cnt = 0;
    for (int i = tid; i < 1024; i += 256) p += g_fin2[i];
    for (int i = tid; i < 65536; i += 256) cnt += (c1[i] != 0) + (c2[i] != 0);
    rs[tid] = a; ri[tid] = cnt;
    __syncthreads();
    for (int s = 128; s; s >>= 1) {
        if (tid < s) { rs[tid] += rs[tid + s]; ri[tid] += ri[tid + s]; }
        __syncthreads();
    }
    float ins_sum = rs[0];
    int nvalid = ri[0];
    __syncthreads();
    rs[tid] = p;
    __syncthreads();
    for (int s = 128; s; s >>= 1) { if (tid < s) rs[tid] += rs[tid + s]; __syncthreads(); }
    if (tid == 0)
        out[0] = ins_sum / (float)N_INS + rs[0] / (float)nvalid;
}

// ---------------------------------------------------------------------------
extern "C" void kernel_launch(void* const* d_in, const int* in_sizes, int n_in,
                              void* d_out, int out_size) {
    const float* v1  = (const float*)d_in[0];
    const float* v2  = (const float*)d_in[1];
    const float* v1p = (const float*)d_in[2];
    const float* v2p = (const float*)d_in[3];
    const int*   c1  = (const int*)d_in[4];
    const int*   c2  = (const int*)d_in[5];
    float* out = (float*)d_out;

    cudaFuncSetAttribute(k_main, cudaFuncAttributeMaxDynamicSharedMemorySize, SM_DYN);

    prep_all<<<2560, 256>>>(v1, v2, v1p, v2p);
    k_main<<<NI_CTAS + 1024, 128, SM_DYN>>>();
    fin_all<<<1536, 256>>>(c1, c2);
    k_combine<<<1, 256>>>(c1, c2, out);
}

// round 13
// speedup vs baseline: 1.1706x; 1.1061x over previous
#include <cuda_runtime.h>
#include <cuda_bf16.h>
#include <cstdint>
#include <math.h>

// ---------------------------------------------------------------------------
// MultiLevelSimCLR, symmetric tiles, 4-warp 64x64-tile HMMA, occ-2,
// single-sync pipelined tiles, fused prep/fin stages, count fused into fin.
// ---------------------------------------------------------------------------

#define B_INS   8192
#define N_INS   16384
#define DDIM    128
#define NPROW   131072
#define L2E10   14.4269504088896340f
#define NI_CTAS 688

// ---- static device scratch ----
__device__ __align__(16) uint32_t g_I[N_INS * 64];       // bf16 instance embs [r][128]
__device__ __align__(16) uint32_t g_P[NPROW * 64];       // bf16 patch embs
__device__ float g_part[128 * 128 * 128];                // [bi][bj][m]  8.4 MB
__device__ float g_pp[256 * 16 * 128];                   // [b][i*4+j][m] 2.1 MB
__device__ float g_fin1[512];
__device__ float g_fin2[1024];
__device__ int   g_cnt2[1024];

__device__ __forceinline__ float ex2f(float x) {
    float y; asm("ex2.approx.f32 %0, %1;" : "=f"(y) : "f"(x)); return y;
}
__device__ __forceinline__ uint32_t smem_u32(const void* p) {
    uint32_t a;
    asm("{ .reg .u64 t; cvta.to.shared.u64 t, %1; cvt.u32.u64 %0, t; }" : "=r"(a) : "l"(p));
    return a;
}
__device__ __forceinline__ void mma16816(float* c, const uint32_t* a, uint32_t b0, uint32_t b1) {
    asm volatile(
        "mma.sync.aligned.m16n8k16.row.col.f32.bf16.bf16.f32 "
        "{%0,%1,%2,%3}, {%4,%5,%6,%7}, {%8,%9}, {%0,%1,%2,%3};"
        : "+f"(c[0]), "+f"(c[1]), "+f"(c[2]), "+f"(c[3])
        : "r"(a[0]), "r"(a[1]), "r"(a[2]), "r"(a[3]), "r"(b0), "r"(b1));
}
__device__ __forceinline__ void ldsm_x4(uint32_t* r, uint32_t addr) {
    asm volatile("ldmatrix.sync.aligned.m8n8.x4.shared.b16 {%0,%1,%2,%3}, [%4];"
        : "=r"(r[0]), "=r"(r[1]), "=r"(r[2]), "=r"(r[3]) : "r"(addr));
}
#define CP_ASYNC16(dst, src) asm volatile("cp.async.cg.shared.global [%0], [%1], 16;" :: "r"(dst), "l"(src))
#define CP_COMMIT()  asm volatile("cp.async.commit_group;" ::: "memory")
#define CP_WAIT0()   asm volatile("cp.async.wait_group 0;" ::: "memory")

// SMEM: A @0 (32KB), B0 @32768, B1 @65536, red[2] @98304 (2 x 2048B)
#define SM_A    0u
#define SM_B0   32768u
#define SM_RED  98304
#define SM_DYN  (98304 + 4096)

// copy a 128x128 bf16 tile global->smem, chunk-swizzled (128 threads)
__device__ __forceinline__ void cpa_tile(uint32_t dst, const char* __restrict__ src) {
    int tid = threadIdx.x;
#pragma unroll
    for (int i = 0; i < 16; i++) {
        int c = tid + i * 128;
        int r = c >> 4, cc = c & 15;
        uint32_t d = dst + r * 256 + (((uint32_t)(cc ^ (r & 7))) << 4);
        CP_ASYNC16(d, src + r * 256 + cc * 16);
    }
}

// ---------------------------------------------------------------------------
// Fused prep: blocks 0..511 instance, 512..2559 patch.
// ---------------------------------------------------------------------------
__global__ void prep_all(const float* __restrict__ v1, const float* __restrict__ v2,
                         const float* __restrict__ v1p, const float* __restrict__ v2p) {
    __shared__ float sb[2][32][129];
    int tid = threadIdx.x, lane = tid & 31, wid = tid >> 5;

    if (blockIdx.x < 512) {
        int gw = (blockIdx.x * 256 + tid) >> 5;
        for (int r = gw; r < N_INS; r += 4096) {
            const float* src = (r < B_INS) ? v1 + (size_t)r * DDIM : v2 + (size_t)(r - B_INS) * DDIM;
            float4 x = ((const float4*)src)[lane];
            float ss = x.x * x.x + x.y * x.y + x.z * x.z + x.w * x.w;
#pragma unroll
            for (int o = 16; o; o >>= 1) ss += __shfl_xor_sync(~0u, ss, o);
            float ri = 1.0f / fmaxf(sqrtf(ss), 1e-12f);
            __nv_bfloat162 p0 = __floats2bfloat162_rn(x.x * ri, x.y * ri);
            __nv_bfloat162 p1 = __floats2bfloat162_rn(x.z * ri, x.w * ri);
            ((uint2*)g_I)[(size_t)r * 32 + lane] = make_uint2(*(uint32_t*)&p0, *(uint32_t*)&p1);
        }
        return;
    }

    int pc = blockIdx.x - 512;
    int j0 = (pc & 7) * 32;
    int b = pc >> 3;
    const float* srcs[2] = { v1p + (size_t)b * DDIM * 256, v2p + (size_t)b * DDIM * 256 };
#pragma unroll
    for (int s = 0; s < 2; s++) {
        const float* src = srcs[s];
        for (int i = 0; i < 16; i++) {
            int idx = tid + i * 256;
            int k = idx >> 5, jj = idx & 31;
            sb[s][jj][k] = src[(size_t)k * 256 + j0 + jj];
        }
    }
    __syncthreads();
    for (int t = 0; t < 8; t++) {
        int rr = wid * 8 + t;
        int s = rr >> 5, jj = rr & 31;
        float x0 = sb[s][jj][lane * 4 + 0];
        float x1 = sb[s][jj][lane * 4 + 1];
        float x2 = sb[s][jj][lane * 4 + 2];
        float x3 = sb[s][jj][lane * 4 + 3];
        float ss = x0 * x0 + x1 * x1 + x2 * x2 + x3 * x3;
#pragma unroll
        for (int o = 16; o; o >>= 1) ss += __shfl_xor_sync(~0u, ss, o);
        float ri = 1.0f / fmaxf(sqrtf(ss), 1e-12f);
        __nv_bfloat162 p0 = __floats2bfloat162_rn(x0 * ri, x1 * ri);
        __nv_bfloat162 p1 = __floats2bfloat162_rn(x2 * ri, x3 * ri);
        size_t row = (size_t)b * 512 + s * 256 + j0 + jj;
        ((uint2*)g_P)[row * 32 + lane] = make_uint2(*(uint32_t*)&p0, *(uint32_t*)&p1);
    }
}

// ---------------------------------------------------------------------------
// Main kernel: 128 threads, 4 warps as 2(M) x 2(N), 64x64 per warp.
// One __syncthreads per tile; prefetch(i+1) issued at tile top.
// ---------------------------------------------------------------------------
__global__ void __launch_bounds__(128, 2) k_main() {
    extern __shared__ char sm[];
    uint32_t sbu = smem_u32(sm);

    int tid = threadIdx.x, lane = tid & 31, wid = tid >> 5;
    int g = lane >> 2, t = lane & 3;
    int l7 = lane & 7, l15 = lane & 15, hi = lane >> 4;
    int warpM = wid >> 1, warpN = wid & 1;
    int woff = warpM * 64, noff = warpN * 64;

    int bid = blockIdx.x;
    const char* Asrc;
    const char* Bembs;
    float* partBase;
    int pairStrideRow;
    int rowIdx;
    int bj0, bjstep, L;

    if (bid < NI_CTAS) {
        int x, slot, ns;
        if (bid < 512)      { x = bid >> 3;               slot = bid & 7;         ns = 8; }
        else if (bid < 640) { x = 64 + ((bid - 512) >> 2); slot = (bid - 512) & 3; ns = 4; }
        else if (bid < 672) { x = 96 + ((bid - 640) >> 1); slot = (bid - 640) & 1; ns = 2; }
        else                { x = 112 + (bid - 672);       slot = 0;               ns = 1; }
        rowIdx = x;
        bj0 = x + slot; bjstep = ns;
        L = (bj0 <= 127) ? ((127 - bj0) / ns) + 1 : 0;
        Asrc = (const char*)g_I + (size_t)x * 32768;
        Bembs = (const char*)g_I;
        partBase = g_part;
        pairStrideRow = 128;
    } else {
        int pc = bid - NI_CTAS;
        int b = pc >> 2, bi = pc & 3;
        rowIdx = bi;
        bj0 = bi; bjstep = 1;
        L = 4 - bi;
        Asrc = (const char*)g_P + ((size_t)b * 512 + (size_t)bi * 128) * 256;
        Bembs = (const char*)g_P + (size_t)b * 512 * 256;
        partBase = g_pp + (size_t)b * 16 * 128;
        pairStrideRow = 4;
    }
    if (L <= 0) return;

    // prologue: A + B0 in one group
    cpa_tile(sbu + SM_A, Asrc);
    cpa_tile(sbu + SM_B0, Bembs + (size_t)bj0 * 32768);
    CP_COMMIT();

    uint32_t aAddr = sbu + SM_A + (uint32_t)(woff + l15) * 256;
    uint32_t bRowOff = (uint32_t)(noff + l15) * 256;

    float* outRprev = 0;
    float* outCprev = 0;
    bool diagprev = false;

    for (int i = 0; i < L; i++) {
        int bj = bj0 + i * bjstep;
        bool diag = (bj == rowIdx);

        CP_WAIT0();
        __syncthreads();

        // flush previous tile's reduced partials (red[(i-1)&1])
        if (i > 0) {
            float* rr = (float*)(sm + SM_RED + ((i - 1) & 1) * 2048);
            outRprev[tid] = rr[tid] + rr[128 + tid];
            if (!diagprev) outCprev[tid] = rr[256 + tid] + rr[384 + tid];
        }

        // prefetch tile i+1 into the buffer tile i-1 used (readers passed sync)
        if (i + 1 < L) {
            cpa_tile(sbu + SM_B0 + ((uint32_t)((i + 1) & 1) << 15),
                     Bembs + (size_t)(bj + bjstep) * 32768);
            CP_COMMIT();
        }

        uint32_t bbuf = sbu + SM_B0 + ((uint32_t)(i & 1) << 15);
        uint32_t bRow = bbuf + bRowOff;

        float acc[4][8][4];
#pragma unroll
        for (int mi = 0; mi < 4; mi++)
#pragma unroll
            for (int ni = 0; ni < 8; ni++)
#pragma unroll
                for (int q = 0; q < 4; q++) acc[mi][ni][q] = 0.f;

#pragma unroll
        for (int ks = 0; ks < 8; ks++) {
            uint32_t coff = (uint32_t)((((ks << 1) | hi) ^ l7) << 4);
            uint32_t a[4][4];
#pragma unroll
            for (int mi = 0; mi < 4; mi++)
                ldsm_x4(a[mi], aAddr + mi * 16 * 256 + coff);
            uint32_t b[4][4];
#pragma unroll
            for (int nj = 0; nj < 4; nj++)
                ldsm_x4(b[nj], bRow + nj * 16 * 256 + coff);
#pragma unroll
            for (int nj = 0; nj < 4; nj++)
#pragma unroll
                for (int mi = 0; mi < 4; mi++) {
                    mma16816(acc[mi][nj * 2 + 0], a[mi], b[nj][0], b[nj][2]);
                    mma16816(acc[mi][nj * 2 + 1], a[mi], b[nj][1], b[nj][3]);
                }
        }

        // epilogue: e = exp(10d - 10); row + col sums into red[i&1]
        float rsum[4][2];
        float csum[16];
#pragma unroll
        for (int mi = 0; mi < 4; mi++) { rsum[mi][0] = 0.f; rsum[mi][1] = 0.f; }
#pragma unroll
        for (int k2 = 0; k2 < 16; k2++) csum[k2] = 0.f;

#pragma unroll
        for (int mi = 0; mi < 4; mi++)
#pragma unroll
            for (int ni = 0; ni < 8; ni++)
#pragma unroll
                for (int q = 0; q < 4; q++) {
                    float e = ex2f(fmaf(acc[mi][ni][q], L2E10, -L2E10));
                    rsum[mi][q >> 1] += e;
                    csum[ni * 2 + (q & 1)] += e;
                }

        float* red = (float*)(sm + SM_RED + (i & 1) * 2048);
#pragma unroll
        for (int mi = 0; mi < 4; mi++)
#pragma unroll
            for (int h = 0; h < 2; h++) {
                float v = rsum[mi][h];
                v += __shfl_xor_sync(~0u, v, 1);
                v += __shfl_xor_sync(~0u, v, 2);
                if (t == 0) red[warpN * 128 + woff + mi * 16 + h * 8 + g] = v;
            }
#pragma unroll
        for (int k2 = 0; k2 < 16; k2++) {
            float v = csum[k2];
            v += __shfl_xor_sync(~0u, v, 4);
            v += __shfl_xor_sync(~0u, v, 8);
            v += __shfl_xor_sync(~0u, v, 16);
            if (g == 0) red[256 + warpM * 128 + noff + (k2 >> 1) * 8 + t * 2 + (k2 & 1)] = v;
        }

        outRprev = partBase + (size_t)(rowIdx * pairStrideRow + bj) * 128;
        outCprev = partBase + (size_t)(bj * pairStrideRow + rowIdx) * 128;
        diagprev = diag;
    }

    __syncthreads();
    {
        float* rr = (float*)(sm + SM_RED + ((L - 1) & 1) * 2048);
        outRprev[tid] = rr[tid] + rr[128 + tid];
        if (!diagprev) outCprev[tid] = rr[256 + tid] + rr[384 + tid];
    }
}

// ---------------------------------------------------------------------------
// Fused fixup: blocks 0..511 instance quarters, 512..1535 patch (+ count).
// ---------------------------------------------------------------------------
__device__ __forceinline__ void dots_row(const uint2* a, const uint2* b, int lane,
                                         float& pos, float& dia) {
    uint2 ua = a[lane], ub = b[lane];
    __nv_bfloat162 a0 = *(__nv_bfloat162*)&ua.x, a1 = *(__nv_bfloat162*)&ua.y;
    __nv_bfloat162 b0 = *(__nv_bfloat162*)&ub.x, b1 = *(__nv_bfloat162*)&ub.y;
    float ax0 = __bfloat162float(a0.x), ax1 = __bfloat162float(a0.y);
    float ax2 = __bfloat162float(a1.x), ax3 = __bfloat162float(a1.y);
    float bx0 = __bfloat162float(b0.x), bx1 = __bfloat162float(b0.y);
    float bx2 = __bfloat162float(b1.x), bx3 = __bfloat162float(b1.y);
    pos = ax0 * bx0 + ax1 * bx1 + ax2 * bx2 + ax3 * bx3;
    dia = ax0 * ax0 + ax1 * ax1 + ax2 * ax2 + ax3 * ax3;
#pragma unroll
    for (int o = 16; o; o >>= 1) {
        pos += __shfl_xor_sync(~0u, pos, o);
        dia += __shfl_xor_sync(~0u, dia, o);
    }
}

__global__ void fin_all(const int* __restrict__ c1, const int* __restrict__ c2) {
    __shared__ float S2a[8][32];
    __shared__ float S2b[256];
    __shared__ float S[128];
    __shared__ float rs[256];
    __shared__ int ric[8];
    int tid = threadIdx.x;
    int lane = tid & 31, wid = tid >> 5;

    if (blockIdx.x < 512) {
        int bi = blockIdx.x >> 2, q = blockIdx.x & 3;
        int m = tid & 31, jg = tid >> 5;

        const float* base = g_part + (size_t)bi * 128 * 128 + q * 32 + m;
        float s = 0.0f;
#pragma unroll
        for (int j = jg * 16; j < jg * 16 + 16; j++) s += base[(size_t)j * 128];
        S2a[jg][m] = s;
        __syncthreads();
        if (tid < 32) {
            float v = 0.0f;
#pragma unroll
            for (int j = 0; j < 8; j++) v += S2a[j][tid];
            S[tid] = v;
        }
        __syncthreads();

        float acc = 0.0f;
#pragma unroll
        for (int ii = 0; ii < 4; ii++) {
            int mm = wid * 4 + ii;
            int r = bi * 128 + q * 32 + mm;
            float pos, dia;
            dots_row(((const uint2*)g_I) + (size_t)r * 32,
                     ((const uint2*)g_I) + (size_t)(r ^ B_INS) * 32, lane, pos, dia);
            if (lane == 0) {
                float Sv = S[mm] - ex2f(fmaf(dia, L2E10, -L2E10));
                acc += 10.0f + logf(Sv) - 10.0f * pos;
            }
        }
        if (lane == 0) rs[wid] = acc;
        __syncthreads();
        if (tid == 0) {
            float v = 0.0f;
#pragma unroll
            for (int i = 0; i < 8; i++) v += rs[i];
            g_fin1[blockIdx.x] = v;
        }
        return;
    }

    int pc = blockIdx.x - 512;
    int b = pc >> 2, bi = pc & 3;
    int m = tid & 127, jh = tid >> 7;

    const float* base = g_pp + ((size_t)b * 16 + bi * 4) * 128 + m;
    float s = 0.0f;
#pragma unroll
    for (int j = jh * 2; j < jh * 2 + 2; j++) s += base[(size_t)j * 128];
    S2b[tid] = s;
    __syncthreads();
    if (tid < 128) S[tid] = S2b[tid] + S2b[tid + 128];
    __syncthreads();

    float acc = 0.0f;
    int cnt = 0;
#pragma unroll 4
    for (int ii = 0; ii < 16; ii++) {
        int mm = wid * 16 + ii;
        int rl = bi * 128 + mm;
        int r = b * 512 + rl;
        int c = (rl < 256) ? c1[b * 256 + rl] : c2[b * 256 + rl - 256];
        float pos, dia;
        dots_row(((const uint2*)g_P) + (size_t)r * 32,
                 ((const uint2*)g_P) + (size_t)(r ^ 256) * 32, lane, pos, dia);
        if (lane == 0 && c != 0) {
            float Sv = S[mm] - ex2f(fmaf(dia, L2E10, -L2E10));
            acc += 10.0f + logf(Sv) - 10.0f * pos;
            cnt++;
        }
    }
    if (lane == 0) { rs[wid] = acc; ric[wid] = cnt; }
    __syncthreads();
    if (tid == 0) {
        float v = 0.0f;
        int cv = 0;
#pragma unroll
        for (int i = 0; i < 8; i++) { v += rs[i]; cv += ric[i]; }
        g_fin2[pc] = v;
        g_cnt2[pc] = cv;
    }
}

__global__ void k_combine(float* __restrict__ out) {
    __shared__ float rs[256];
    __shared__ int ri[256];
    int tid = threadIdx.x;
    float a = g_fin1[tid] + g_fin1[tid + 256];
    float p = g_fin2[tid] + g_fin2[tid + 256] + g_fin2[tid + 512] + g_fin2[tid + 768];
    int cnt = g_cnt2[tid] + g_cnt2[tid + 256] + g_cnt2[tid + 512] + g_cnt2[tid + 768];
    rs[tid] = a; ri[tid] = cnt;
    __syncthreads();
    for (int s = 128; s; s >>= 1) {
        if (tid < s) { rs[tid] += rs[tid + s]; ri[tid] += ri[tid + s]; }
        __syncthreads();
    }
    float ins_sum = rs[0];
    int nvalid = ri[0];
    __syncthreads();
    rs[tid] = p;
    __syncthreads();
    for (int s = 128; s; s >>= 1) { if (tid < s) rs[tid] += rs[tid + s]; __syncthreads(); }
    if (tid == 0)
        out[0] = ins_sum / (float)N_INS + rs[0] / (float)nvalid;
}

// ---------------------------------------------------------------------------
extern "C" void kernel_launch(void* const* d_in, const int* in_sizes, int n_in,
                              void* d_out, int out_size) {
    const float* v1  = (const float*)d_in[0];
    const float* v2  = (const float*)d_in[1];
    const float* v1p = (const float*)d_in[2];
    const float* v2p = (const float*)d_in[3];
    const int*   c1  = (const int*)d_in[4];
    const int*   c2  = (const int*)d_in[5];
    float* out = (float*)d_out;

    cudaFuncSetAttribute(k_main, cudaFuncAttributeMaxDynamicSharedMemorySize, SM_DYN);

    prep_all<<<2560, 256>>>(v1, v2, v1p, v2p);
    k_main<<<NI_CTAS + 1024, 128, SM_DYN>>>();
    fin_all<<<1536, 256>>>(c1, c2);
    k_combine<<<1, 256>>>(out);
}

// round 14
// speedup vs baseline: 1.2445x; 1.0632x over previous
#include <cuda_runtime.h>
#include <cuda_bf16.h>
#include <cuda_fp16.h>
#include <cstdint>
#include <math.h>

// ---------------------------------------------------------------------------
// MultiLevelSimCLR: symmetric tiles, 4-warp 64x64 HMMA, occ-2, f16x2 exp
// epilogue (fp32 args + fp32 accumulation), in-kernel diagonal masking,
// last-block-fused final combine.
// ---------------------------------------------------------------------------

#define B_INS   8192
#define N_INS   16384
#define DDIM    128
#define NPROW   131072
#define L2E10   14.4269504088896340f
#define NI_CTAS 688

// ---- static device scratch ----
__device__ __align__(16) uint32_t g_I[N_INS * 64];       // bf16 instance embs [r][128]
__device__ __align__(16) uint32_t g_P[NPROW * 64];       // bf16 patch embs
__device__ float g_part[128 * 128 * 128];                // [bi][bj][m]  8.4 MB
__device__ float g_pp[256 * 16 * 128];                   // [b][i*4+j][m] 2.1 MB
__device__ float g_fin1[512];
__device__ float g_fin2[1024];
__device__ int   g_cnt2[1024];
__device__ int   g_done;

__device__ __forceinline__ __half2 h2ex2(__half2 x) {
    uint32_t xi = *(uint32_t*)&x, yi;
    asm("ex2.approx.f16x2 %0, %1;" : "=r"(yi) : "r"(xi));
    return *(__half2*)&yi;
}
__device__ __forceinline__ uint32_t smem_u32(const void* p) {
    uint32_t a;
    asm("{ .reg .u64 t; cvta.to.shared.u64 t, %1; cvt.u32.u64 %0, t; }" : "=r"(a) : "l"(p));
    return a;
}
__device__ __forceinline__ void mma16816(float* c, const uint32_t* a, uint32_t b0, uint32_t b1) {
    asm volatile(
        "mma.sync.aligned.m16n8k16.row.col.f32.bf16.bf16.f32 "
        "{%0,%1,%2,%3}, {%4,%5,%6,%7}, {%8,%9}, {%0,%1,%2,%3};"
        : "+f"(c[0]), "+f"(c[1]), "+f"(c[2]), "+f"(c[3])
        : "r"(a[0]), "r"(a[1]), "r"(a[2]), "r"(a[3]), "r"(b0), "r"(b1));
}
__device__ __forceinline__ void ldsm_x4(uint32_t* r, uint32_t addr) {
    asm volatile("ldmatrix.sync.aligned.m8n8.x4.shared.b16 {%0,%1,%2,%3}, [%4];"
        : "=r"(r[0]), "=r"(r[1]), "=r"(r[2]), "=r"(r[3]) : "r"(addr));
}
#define CP_ASYNC16(dst, src) asm volatile("cp.async.cg.shared.global [%0], [%1], 16;" :: "r"(dst), "l"(src))
#define CP_COMMIT()  asm volatile("cp.async.commit_group;" ::: "memory")
#define CP_WAIT0()   asm volatile("cp.async.wait_group 0;" ::: "memory")

// SMEM: A @0 (32KB), B0 @32768, B1 @65536, red[2] @98304 (2 x 2048B)
#define SM_A    0u
#define SM_B0   32768u
#define SM_RED  98304
#define SM_DYN  (98304 + 4096)

__device__ __forceinline__ void cpa_tile(uint32_t dst, const char* __restrict__ src) {
    int tid = threadIdx.x;
#pragma unroll
    for (int i = 0; i < 16; i++) {
        int c = tid + i * 128;
        int r = c >> 4, cc = c & 15;
        uint32_t d = dst + r * 256 + (((uint32_t)(cc ^ (r & 7))) << 4);
        CP_ASYNC16(d, src + r * 256 + cc * 16);
    }
}

// ---------------------------------------------------------------------------
// Fused prep: blocks 0..511 instance, 512..2559 patch.
// ---------------------------------------------------------------------------
__global__ void prep_all(const float* __restrict__ v1, const float* __restrict__ v2,
                         const float* __restrict__ v1p, const float* __restrict__ v2p) {
    __shared__ float sb[2][32][129];
    int tid = threadIdx.x, lane = tid & 31, wid = tid >> 5;

    if (blockIdx.x < 512) {
        int gw = (blockIdx.x * 256 + tid) >> 5;
        for (int r = gw; r < N_INS; r += 4096) {
            const float* src = (r < B_INS) ? v1 + (size_t)r * DDIM : v2 + (size_t)(r - B_INS) * DDIM;
            float4 x = ((const float4*)src)[lane];
            float ss = x.x * x.x + x.y * x.y + x.z * x.z + x.w * x.w;
#pragma unroll
            for (int o = 16; o; o >>= 1) ss += __shfl_xor_sync(~0u, ss, o);
            float ri = 1.0f / fmaxf(sqrtf(ss), 1e-12f);
            __nv_bfloat162 p0 = __floats2bfloat162_rn(x.x * ri, x.y * ri);
            __nv_bfloat162 p1 = __floats2bfloat162_rn(x.z * ri, x.w * ri);
            ((uint2*)g_I)[(size_t)r * 32 + lane] = make_uint2(*(uint32_t*)&p0, *(uint32_t*)&p1);
        }
        return;
    }

    int pc = blockIdx.x - 512;
    int j0 = (pc & 7) * 32;
    int b = pc >> 3;
    const float* srcs[2] = { v1p + (size_t)b * DDIM * 256, v2p + (size_t)b * DDIM * 256 };
#pragma unroll
    for (int s = 0; s < 2; s++) {
        const float* src = srcs[s];
        for (int i = 0; i < 16; i++) {
            int idx = tid + i * 256;
            int k = idx >> 5, jj = idx & 31;
            sb[s][jj][k] = src[(size_t)k * 256 + j0 + jj];
        }
    }
    __syncthreads();
    for (int t = 0; t < 8; t++) {
        int rr = wid * 8 + t;
        int s = rr >> 5, jj = rr & 31;
        float x0 = sb[s][jj][lane * 4 + 0];
        float x1 = sb[s][jj][lane * 4 + 1];
        float x2 = sb[s][jj][lane * 4 + 2];
        float x3 = sb[s][jj][lane * 4 + 3];
        float ss = x0 * x0 + x1 * x1 + x2 * x2 + x3 * x3;
#pragma unroll
        for (int o = 16; o; o >>= 1) ss += __shfl_xor_sync(~0u, ss, o);
        float ri = 1.0f / fmaxf(sqrtf(ss), 1e-12f);
        __nv_bfloat162 p0 = __floats2bfloat162_rn(x0 * ri, x1 * ri);
        __nv_bfloat162 p1 = __floats2bfloat162_rn(x2 * ri, x3 * ri);
        size_t row = (size_t)b * 512 + s * 256 + j0 + jj;
        ((uint2*)g_P)[row * 32 + lane] = make_uint2(*(uint32_t*)&p0, *(uint32_t*)&p1);
    }
}

// epilogue micro-block for one (mi, ni): f16x2 exp, fp32 sums
#define EPI_BLOCK(MASKED)                                                       \
    {                                                                           \
        float a0 = acc[mi][ni][0] * L2E10;                                      \
        float a1 = acc[mi][ni][1] * L2E10;                                      \
        float a2 = acc[mi][ni][2] * L2E10;                                      \
        float a3 = acc[mi][ni][3] * L2E10;                                      \
        if (MASKED) {                                                           \
            int r0 = woff + mi * 16 + g, r1 = r0 + 8;                           \
            int c0 = noff + ni * 8 + t * 2, c1 = c0 + 1;                        \
            if (r0 == c0) a0 = -1e4f;                                           \
            if (r0 == c1) a1 = -1e4f;                                           \
            if (r1 == c0) a2 = -1e4f;                                           \
            if (r1 == c1) a3 = -1e4f;                                           \
        }                                                                       \
        __half2 h0 = h2ex2(__floats2half2_rn(a0, a1));                          \
        __half2 h1 = h2ex2(__floats2half2_rn(a2, a3));                          \
        float2 e01 = __half22float2(h0);                                        \
        float2 e23 = __half22float2(h1);                                        \
        rsum[mi][0] += e01.x + e01.y;                                           \
        rsum[mi][1] += e23.x + e23.y;                                           \
        csum[ni * 2 + 0] += e01.x + e23.x;                                      \
        csum[ni * 2 + 1] += e01.y + e23.y;                                      \
    }

// ---------------------------------------------------------------------------
// Main kernel: 128 threads, 4 warps as 2(M) x 2(N), 64x64 per warp.
// ---------------------------------------------------------------------------
__global__ void __launch_bounds__(128, 2) k_main() {
    extern __shared__ char sm[];
    uint32_t sbu = smem_u32(sm);

    int tid = threadIdx.x, lane = tid & 31, wid = tid >> 5;
    int g = lane >> 2, t = lane & 3;
    int l7 = lane & 7, l15 = lane & 15, hi = lane >> 4;
    int warpM = wid >> 1, warpN = wid & 1;
    int woff = warpM * 64, noff = warpN * 64;

    int bid = blockIdx.x;
    const char* Asrc;
    const char* Bembs;
    float* partBase;
    int pairStrideRow;
    int rowIdx;
    int bj0, bjstep, L;

    if (bid < NI_CTAS) {
        int x, slot, ns;
        if (bid < 512)      { x = bid >> 3;               slot = bid & 7;         ns = 8; }
        else if (bid < 640) { x = 64 + ((bid - 512) >> 2); slot = (bid - 512) & 3; ns = 4; }
        else if (bid < 672) { x = 96 + ((bid - 640) >> 1); slot = (bid - 640) & 1; ns = 2; }
        else                { x = 112 + (bid - 672);       slot = 0;               ns = 1; }
        rowIdx = x;
        bj0 = x + slot; bjstep = ns;
        L = (bj0 <= 127) ? ((127 - bj0) / ns) + 1 : 0;
        Asrc = (const char*)g_I + (size_t)x * 32768;
        Bembs = (const char*)g_I;
        partBase = g_part;
        pairStrideRow = 128;
    } else {
        int pc = bid - NI_CTAS;
        int b = pc >> 2, bi = pc & 3;
        rowIdx = bi;
        bj0 = bi; bjstep = 1;
        L = 4 - bi;
        Asrc = (const char*)g_P + ((size_t)b * 512 + (size_t)bi * 128) * 256;
        Bembs = (const char*)g_P + (size_t)b * 512 * 256;
        partBase = g_pp + (size_t)b * 16 * 128;
        pairStrideRow = 4;
    }
    if (L <= 0) return;

    cpa_tile(sbu + SM_A, Asrc);
    cpa_tile(sbu + SM_B0, Bembs + (size_t)bj0 * 32768);
    CP_COMMIT();

    uint32_t aAddr = sbu + SM_A + (uint32_t)(woff + l15) * 256;
    uint32_t bRowOff = (uint32_t)(noff + l15) * 256;

    float* outRprev = 0;
    float* outCprev = 0;
    bool diagprev = false;

    for (int i = 0; i < L; i++) {
        int bj = bj0 + i * bjstep;
        bool diag = (bj == rowIdx);
        bool diagW = diag && (warpM == warpN);

        CP_WAIT0();
        __syncthreads();

        if (i > 0) {
            float* rr = (float*)(sm + SM_RED + ((i - 1) & 1) * 2048);
            outRprev[tid] = rr[tid] + rr[128 + tid];
            if (!diagprev) outCprev[tid] = rr[256 + tid] + rr[384 + tid];
        }

        if (i + 1 < L) {
            cpa_tile(sbu + SM_B0 + ((uint32_t)((i + 1) & 1) << 15),
                     Bembs + (size_t)(bj + bjstep) * 32768);
            CP_COMMIT();
        }

        uint32_t bbuf = sbu + SM_B0 + ((uint32_t)(i & 1) << 15);
        uint32_t bRow = bbuf + bRowOff;

        float acc[4][8][4];
#pragma unroll
        for (int mi = 0; mi < 4; mi++)
#pragma unroll
            for (int ni = 0; ni < 8; ni++)
#pragma unroll
                for (int q = 0; q < 4; q++) acc[mi][ni][q] = 0.f;

#pragma unroll
        for (int ks = 0; ks < 8; ks++) {
            uint32_t coff = (uint32_t)((((ks << 1) | hi) ^ l7) << 4);
            uint32_t a[4][4];
#pragma unroll
            for (int mi = 0; mi < 4; mi++)
                ldsm_x4(a[mi], aAddr + mi * 16 * 256 + coff);
            uint32_t b[4][4];
#pragma unroll
            for (int nj = 0; nj < 4; nj++)
                ldsm_x4(b[nj], bRow + nj * 16 * 256 + coff);
#pragma unroll
            for (int nj = 0; nj < 4; nj++)
#pragma unroll
                for (int mi = 0; mi < 4; mi++) {
                    mma16816(acc[mi][nj * 2 + 0], a[mi], b[nj][0], b[nj][2]);
                    mma16816(acc[mi][nj * 2 + 1], a[mi], b[nj][1], b[nj][3]);
                }
        }

        // epilogue: e = exp(10d) via f16x2 ex2 (fp32 args/accum)
        float rsum[4][2];
        float csum[16];
#pragma unroll
        for (int mi = 0; mi < 4; mi++) { rsum[mi][0] = 0.f; rsum[mi][1] = 0.f; }
#pragma unroll
        for (int k2 = 0; k2 < 16; k2++) csum[k2] = 0.f;

        if (diagW) {
#pragma unroll
            for (int mi = 0; mi < 4; mi++)
#pragma unroll
                for (int ni = 0; ni < 8; ni++) EPI_BLOCK(true);
        } else {
#pragma unroll
            for (int mi = 0; mi < 4; mi++)
#pragma unroll
                for (int ni = 0; ni < 8; ni++) EPI_BLOCK(false);
        }

        float* red = (float*)(sm + SM_RED + (i & 1) * 2048);
#pragma unroll
        for (int mi = 0; mi < 4; mi++)
#pragma unroll
            for (int h = 0; h < 2; h++) {
                float v = rsum[mi][h];
                v += __shfl_xor_sync(~0u, v, 1);
                v += __shfl_xor_sync(~0u, v, 2);
                if (t == 0) red[warpN * 128 + woff + mi * 16 + h * 8 + g] = v;
            }
#pragma unroll
        for (int k2 = 0; k2 < 16; k2++) {
            float v = csum[k2];
            v += __shfl_xor_sync(~0u, v, 4);
            v += __shfl_xor_sync(~0u, v, 8);
            v += __shfl_xor_sync(~0u, v, 16);
            if (g == 0) red[256 + warpM * 128 + noff + (k2 >> 1) * 8 + t * 2 + (k2 & 1)] = v;
        }

        outRprev = partBase + (size_t)(rowIdx * pairStrideRow + bj) * 128;
        outCprev = partBase + (size_t)(bj * pairStrideRow + rowIdx) * 128;
        diagprev = diag;
    }

    __syncthreads();
    {
        float* rr = (float*)(sm + SM_RED + ((L - 1) & 1) * 2048);
        outRprev[tid] = rr[tid] + rr[128 + tid];
        if (!diagprev) outCprev[tid] = rr[256 + tid] + rr[384 + tid];
    }
}

// ---------------------------------------------------------------------------
// Fused fixup + final combine (last-block). loss_r = log(S_r) - 10*pos.
// ---------------------------------------------------------------------------
__device__ __forceinline__ float dot_row(const uint2* a, const uint2* b, int lane) {
    uint2 ua = a[lane], ub = b[lane];
    __nv_bfloat162 a0 = *(__nv_bfloat162*)&ua.x, a1 = *(__nv_bfloat162*)&ua.y;
    __nv_bfloat162 b0 = *(__nv_bfloat162*)&ub.x, b1 = *(__nv_bfloat162*)&ub.y;
    float pos = __bfloat162float(a0.x) * __bfloat162float(b0.x)
              + __bfloat162float(a0.y) * __bfloat162float(b0.y)
              + __bfloat162float(a1.x) * __bfloat162float(b1.x)
              + __bfloat162float(a1.y) * __bfloat162float(b1.y);
#pragma unroll
    for (int o = 16; o; o >>= 1) pos += __shfl_xor_sync(~0u, pos, o);
    return pos;
}

__global__ void fin_all(const int* __restrict__ c1, const int* __restrict__ c2,
                        float* __restrict__ out) {
    __shared__ float S2a[8][32];
    __shared__ float S2b[256];
    __shared__ float S[128];
    __shared__ float rs[256];
    __shared__ int ric[8];
    __shared__ int sLast;
    int tid = threadIdx.x;
    int lane = tid & 31, wid = tid >> 5;

    if (blockIdx.x < 512) {
        int bi = blockIdx.x >> 2, q = blockIdx.x & 3;
        int m = tid & 31, jg = tid >> 5;

        const float* base = g_part + (size_t)bi * 128 * 128 + q * 32 + m;
        float s = 0.0f;
#pragma unroll
        for (int j = jg * 16; j < jg * 16 + 16; j++) s += base[(size_t)j * 128];
        S2a[jg][m] = s;
        __syncthreads();
        if (tid < 32) {
            float v = 0.0f;
#pragma unroll
            for (int j = 0; j < 8; j++) v += S2a[j][tid];
            S[tid] = v;
        }
        __syncthreads();

        float acc = 0.0f;
#pragma unroll
        for (int ii = 0; ii < 4; ii++) {
            int mm = wid * 4 + ii;
            int r = bi * 128 + q * 32 + mm;
            float pos = dot_row(((const uint2*)g_I) + (size_t)r * 32,
                                ((const uint2*)g_I) + (size_t)(r ^ B_INS) * 32, lane);
            if (lane == 0) acc += logf(S[mm]) - 10.0f * pos;
        }
        if (lane == 0) rs[wid] = acc;
        __syncthreads();
        if (tid == 0) {
            float v = 0.0f;
#pragma unroll
            for (int i = 0; i < 8; i++) v += rs[i];
            g_fin1[blockIdx.x] = v;
        }
    } else {
        int pc = blockIdx.x - 512;
        int b = pc >> 2, bi = pc & 3;
        int m = tid & 127, jh = tid >> 7;

        const float* base = g_pp + ((size_t)b * 16 + bi * 4) * 128 + m;
        float s = 0.0f;
#pragma unroll
        for (int j = jh * 2; j < jh * 2 + 2; j++) s += base[(size_t)j * 128];
        S2b[tid] = s;
        __syncthreads();
        if (tid < 128) S[tid] = S2b[tid] + S2b[tid + 128];
        __syncthreads();

        float acc = 0.0f;
        int cnt = 0;
#pragma unroll 4
        for (int ii = 0; ii < 16; ii++) {
            int mm = wid * 16 + ii;
            int rl = bi * 128 + mm;
            int r = b * 512 + rl;
            int c = (rl < 256) ? c1[b * 256 + rl] : c2[b * 256 + rl - 256];
            float pos = dot_row(((const uint2*)g_P) + (size_t)r * 32,
                                ((const uint2*)g_P) + (size_t)(r ^ 256) * 32, lane);
            if (lane == 0 && c != 0) {
                acc += logf(S[mm]) - 10.0f * pos;
                cnt++;
            }
        }
        if (lane == 0) { rs[wid] = acc; ric[wid] = cnt; }
        __syncthreads();
        if (tid == 0) {
            float v = 0.0f;
            int cv = 0;
#pragma unroll
            for (int i = 0; i < 8; i++) { v += rs[i]; cv += ric[i]; }
            g_fin2[pc] = v;
            g_cnt2[pc] = cv;
        }
    }

    // ---- last block does the final deterministic combine ----
    __threadfence();
    __syncthreads();
    if (tid == 0) {
        int ticket = atomicAdd(&g_done, 1);
        sLast = (ticket == 1535);
    }
    __syncthreads();
    if (!sLast) return;

    __shared__ float frs[256];
    __shared__ int fri[256];
    float a = g_fin1[tid] + g_fin1[tid + 256];
    float p = g_fin2[tid] + g_fin2[tid + 256] + g_fin2[tid + 512] + g_fin2[tid + 768];
    int cnt = g_cnt2[tid] + g_cnt2[tid + 256] + g_cnt2[tid + 512] + g_cnt2[tid + 768];
    frs[tid] = a; fri[tid] = cnt;
    __syncthreads();
    for (int s = 128; s; s >>= 1) {
        if (tid < s) { frs[tid] += frs[tid + s]; fri[tid] += fri[tid + s]; }
        __syncthreads();
    }
    float ins_sum = frs[0];
    int nvalid = fri[0];
    __syncthreads();
    frs[tid] = p;
    __syncthreads();
    for (int s = 128; s; s >>= 1) { if (tid < s) frs[tid] += frs[tid + s]; __syncthreads(); }
    if (tid == 0) {
        out[0] = ins_sum / (float)N_INS + frs[0] / (float)nvalid;
        g_done = 0;   // reset for next graph replay
    }
}

// ---------------------------------------------------------------------------
extern "C" void kernel_launch(void* const* d_in, const int* in_sizes, int n_in,
                              void* d_out, int out_size) {
    const float* v1  = (const float*)d_in[0];
    const float* v2  = (const float*)d_in[1];
    const float* v1p = (const float*)d_in[2];
    const float* v2p = (const float*)d_in[3];
    const int*   c1  = (const int*)d_in[4];
    const int*   c2  = (const int*)d_in[5];
    float* out = (float*)d_out;

    cudaFuncSetAttribute(k_main, cudaFuncAttributeMaxDynamicSharedMemorySize, SM_DYN);

    prep_all<<<2560, 256>>>(v1, v2, v1p, v2p);
    k_main<<<NI_CTAS + 1024, 128, SM_DYN>>>();
    fin_all<<<1536, 256>>>(c1, c2, out);
}

// round 15
// speedup vs baseline: 1.3260x; 1.0655x over previous
#include <cuda_runtime.h>
#include <cuda_bf16.h>
#include <cuda_fp16.h>
#include <cstdint>
#include <math.h>

// ---------------------------------------------------------------------------
// MultiLevelSimCLR: symmetric tiles, 4-warp 64x64 HMMA, occ-2, f16x2 exp
// epilogue, in-kernel diag masking + positive-logit harvesting, slim fixup.
// ---------------------------------------------------------------------------

#define B_INS   8192
#define N_INS   16384
#define DDIM    128
#define NPROW   131072
#define L2E10   14.4269504088896340f
#define NI_CTAS 688

// ---- static device scratch ----
__device__ __align__(16) uint32_t g_I[N_INS * 64];       // bf16 instance embs [r][128]
__device__ __align__(16) uint32_t g_P[NPROW * 64];       // bf16 patch embs
__device__ float g_part[128 * 128 * 128];                // [bi][bj][m]  8.4 MB
__device__ float g_pp[256 * 16 * 128];                   // [b][i*4+j][m] 2.1 MB
__device__ float g_posI[N_INS];                          // positive dots (instance)
__device__ float g_posP[NPROW];                          // positive dots (patch)
__device__ float g_fin1[512];
__device__ float g_fin2[1024];
__device__ int   g_cnt2[1024];
__device__ int   g_done;

__device__ __forceinline__ __half2 h2ex2(__half2 x) {
    uint32_t xi = *(uint32_t*)&x, yi;
    asm("ex2.approx.f16x2 %0, %1;" : "=r"(yi) : "r"(xi));
    return *(__half2*)&yi;
}
__device__ __forceinline__ uint32_t smem_u32(const void* p) {
    uint32_t a;
    asm("{ .reg .u64 t; cvta.to.shared.u64 t, %1; cvt.u32.u64 %0, t; }" : "=r"(a) : "l"(p));
    return a;
}
__device__ __forceinline__ void mma16816(float* c, const uint32_t* a, uint32_t b0, uint32_t b1) {
    asm volatile(
        "mma.sync.aligned.m16n8k16.row.col.f32.bf16.bf16.f32 "
        "{%0,%1,%2,%3}, {%4,%5,%6,%7}, {%8,%9}, {%0,%1,%2,%3};"
        : "+f"(c[0]), "+f"(c[1]), "+f"(c[2]), "+f"(c[3])
        : "r"(a[0]), "r"(a[1]), "r"(a[2]), "r"(a[3]), "r"(b0), "r"(b1));
}
__device__ __forceinline__ void ldsm_x4(uint32_t* r, uint32_t addr) {
    asm volatile("ldmatrix.sync.aligned.m8n8.x4.shared.b16 {%0,%1,%2,%3}, [%4];"
        : "=r"(r[0]), "=r"(r[1]), "=r"(r[2]), "=r"(r[3]) : "r"(addr));
}
#define CP_ASYNC16(dst, src) asm volatile("cp.async.cg.shared.global [%0], [%1], 16;" :: "r"(dst), "l"(src))
#define CP_COMMIT()  asm volatile("cp.async.commit_group;" ::: "memory")
#define CP_WAIT0()   asm volatile("cp.async.wait_group 0;" ::: "memory")

// SMEM: A @0 (32KB), B0 @32768, B1 @65536, red[2] @98304 (2 x 2048B)
#define SM_A    0u
#define SM_B0   32768u
#define SM_RED  98304
#define SM_DYN  (98304 + 4096)

__device__ __forceinline__ void cpa_tile(uint32_t dst, const char* __restrict__ src) {
    int tid = threadIdx.x;
#pragma unroll
    for (int i = 0; i < 16; i++) {
        int c = tid + i * 128;
        int r = c >> 4, cc = c & 15;
        uint32_t d = dst + r * 256 + (((uint32_t)(cc ^ (r & 7))) << 4);
        CP_ASYNC16(d, src + r * 256 + cc * 16);
    }
}

// ---------------------------------------------------------------------------
// Fused prep: blocks 0..511 instance, 512..2559 patch (float4 loads).
// ---------------------------------------------------------------------------
__global__ void prep_all(const float* __restrict__ v1, const float* __restrict__ v2,
                         const float* __restrict__ v1p, const float* __restrict__ v2p) {
    __shared__ float sb[2][32][129];
    int tid = threadIdx.x, lane = tid & 31, wid = tid >> 5;

    if (blockIdx.x < 512) {
        int gw = (blockIdx.x * 256 + tid) >> 5;
        for (int r = gw; r < N_INS; r += 4096) {
            const float* src = (r < B_INS) ? v1 + (size_t)r * DDIM : v2 + (size_t)(r - B_INS) * DDIM;
            float4 x = ((const float4*)src)[lane];
            float ss = x.x * x.x + x.y * x.y + x.z * x.z + x.w * x.w;
#pragma unroll
            for (int o = 16; o; o >>= 1) ss += __shfl_xor_sync(~0u, ss, o);
            float ri = 1.0f / fmaxf(sqrtf(ss), 1e-12f);
            __nv_bfloat162 p0 = __floats2bfloat162_rn(x.x * ri, x.y * ri);
            __nv_bfloat162 p1 = __floats2bfloat162_rn(x.z * ri, x.w * ri);
            ((uint2*)g_I)[(size_t)r * 32 + lane] = make_uint2(*(uint32_t*)&p0, *(uint32_t*)&p1);
        }
        return;
    }

    int pc = blockIdx.x - 512;
    int j0 = (pc & 7) * 32;
    int b = pc >> 3;
    const float* srcs[2] = { v1p + (size_t)b * DDIM * 256, v2p + (size_t)b * DDIM * 256 };
#pragma unroll
    for (int s = 0; s < 2; s++) {
        const float4* src4 = (const float4*)srcs[s];
#pragma unroll
        for (int it = 0; it < 4; it++) {
            int idx = tid + it * 256;          // 0..1023
            int k = idx >> 3, j4 = idx & 7;
            float4 v = src4[k * 64 + (j0 >> 2) + j4];
            sb[s][j4 * 4 + 0][k] = v.x;
            sb[s][j4 * 4 + 1][k] = v.y;
            sb[s][j4 * 4 + 2][k] = v.z;
            sb[s][j4 * 4 + 3][k] = v.w;
        }
    }
    __syncthreads();
    for (int t = 0; t < 8; t++) {
        int rr = wid * 8 + t;
        int s = rr >> 5, jj = rr & 31;
        float x0 = sb[s][jj][lane * 4 + 0];
        float x1 = sb[s][jj][lane * 4 + 1];
        float x2 = sb[s][jj][lane * 4 + 2];
        float x3 = sb[s][jj][lane * 4 + 3];
        float ss = x0 * x0 + x1 * x1 + x2 * x2 + x3 * x3;
#pragma unroll
        for (int o = 16; o; o >>= 1) ss += __shfl_xor_sync(~0u, ss, o);
        float ri = 1.0f / fmaxf(sqrtf(ss), 1e-12f);
        __nv_bfloat162 p0 = __floats2bfloat162_rn(x0 * ri, x1 * ri);
        __nv_bfloat162 p1 = __floats2bfloat162_rn(x2 * ri, x3 * ri);
        size_t row = (size_t)b * 512 + s * 256 + j0 + jj;
        ((uint2*)g_P)[row * 32 + lane] = make_uint2(*(uint32_t*)&p0, *(uint32_t*)&p1);
    }
}

// epilogue micro-block: f16x2 exp, fp32 sums
#define EPI_BLOCK(MASKED)                                                       \
    {                                                                           \
        float a0 = acc[mi][ni][0] * L2E10;                                      \
        float a1 = acc[mi][ni][1] * L2E10;                                      \
        float a2 = acc[mi][ni][2] * L2E10;                                      \
        float a3 = acc[mi][ni][3] * L2E10;                                      \
        if (MASKED) {                                                           \
            int r0 = woff + mi * 16 + g, r1 = r0 + 8;                           \
            int c0 = noff + ni * 8 + t * 2, c1 = c0 + 1;                        \
            if (r0 == c0) a0 = -1e4f;                                           \
            if (r0 == c1) a1 = -1e4f;                                           \
            if (r1 == c0) a2 = -1e4f;                                           \
            if (r1 == c1) a3 = -1e4f;                                           \
        }                                                                       \
        __half2 h0 = h2ex2(__floats2half2_rn(a0, a1));                          \
        __half2 h1 = h2ex2(__floats2half2_rn(a2, a3));                          \
        float2 e01 = __half22float2(h0);                                        \
        float2 e23 = __half22float2(h1);                                        \
        rsum[mi][0] += e01.x + e01.y;                                           \
        rsum[mi][1] += e23.x + e23.y;                                           \
        csum[ni * 2 + 0] += e01.x + e23.x;                                      \
        csum[ni * 2 + 1] += e01.y + e23.y;                                      \
    }

// ---------------------------------------------------------------------------
// Main kernel: 128 threads, 4 warps as 2(M) x 2(N), 64x64 per warp.
// ---------------------------------------------------------------------------
__global__ void __launch_bounds__(128, 2) k_main() {
    extern __shared__ char sm[];
    uint32_t sbu = smem_u32(sm);

    int tid = threadIdx.x, lane = tid & 31, wid = tid >> 5;
    int g = lane >> 2, t = lane & 3;
    int l7 = lane & 7, l15 = lane & 15, hi = lane >> 4;
    int warpM = wid >> 1, warpN = wid & 1;
    int woff = warpM * 64, noff = warpN * 64;

    int bid = blockIdx.x;
    const char* Asrc;
    const char* Bembs;
    float* partBase;
    int pairStrideRow;
    int rowIdx;
    int bj0, bjstep, L;
    int posBj = -1;
    float* posOutA = 0;
    float* posOutB = 0;

    if (bid < NI_CTAS) {
        int x, slot, ns;
        if (bid < 512)      { x = bid >> 3;               slot = bid & 7;         ns = 8; }
        else if (bid < 640) { x = 64 + ((bid - 512) >> 2); slot = (bid - 512) & 3; ns = 4; }
        else if (bid < 672) { x = 96 + ((bid - 640) >> 1); slot = (bid - 640) & 1; ns = 2; }
        else                { x = 112 + (bid - 672);       slot = 0;               ns = 1; }
        rowIdx = x;
        bj0 = x + slot; bjstep = ns;
        L = (bj0 <= 127) ? ((127 - bj0) / ns) + 1 : 0;
        Asrc = (const char*)g_I + (size_t)x * 32768;
        Bembs = (const char*)g_I;
        partBase = g_part;
        pairStrideRow = 128;
        if (x < 64) {
            posBj = x + 64;
            posOutA = g_posI + x * 128;
            posOutB = g_posI + (x + 64) * 128;
        }
    } else {
        int pc = bid - NI_CTAS;
        int b = pc >> 2, bi = pc & 3;
        rowIdx = bi;
        bj0 = bi; bjstep = 1;
        L = 4 - bi;
        Asrc = (const char*)g_P + ((size_t)b * 512 + (size_t)bi * 128) * 256;
        Bembs = (const char*)g_P + (size_t)b * 512 * 256;
        partBase = g_pp + (size_t)b * 16 * 128;
        pairStrideRow = 4;
        if (bi < 2) {
            posBj = bi + 2;
            posOutA = g_posP + (size_t)b * 512 + bi * 128;
            posOutB = g_posP + (size_t)b * 512 + (bi + 2) * 128;
        }
    }
    if (L <= 0) return;

    cpa_tile(sbu + SM_A, Asrc);
    cpa_tile(sbu + SM_B0, Bembs + (size_t)bj0 * 32768);
    CP_COMMIT();

    uint32_t aAddr = sbu + SM_A + (uint32_t)(woff + l15) * 256;
    uint32_t bRowOff = (uint32_t)(noff + l15) * 256;

    float* outRprev = 0;
    float* outCprev = 0;
    bool diagprev = false;

    for (int i = 0; i < L; i++) {
        int bj = bj0 + i * bjstep;
        bool diag = (bj == rowIdx);
        bool diagW = diag && (warpM == warpN);

        CP_WAIT0();
        __syncthreads();

        if (i > 0) {
            float* rr = (float*)(sm + SM_RED + ((i - 1) & 1) * 2048);
            outRprev[tid] = rr[tid] + rr[128 + tid];
            if (!diagprev) outCprev[tid] = rr[256 + tid] + rr[384 + tid];
        }

        if (i + 1 < L) {
            cpa_tile(sbu + SM_B0 + ((uint32_t)((i + 1) & 1) << 15),
                     Bembs + (size_t)(bj + bjstep) * 32768);
            CP_COMMIT();
        }

        uint32_t bbuf = sbu + SM_B0 + ((uint32_t)(i & 1) << 15);
        uint32_t bRow = bbuf + bRowOff;

        float acc[4][8][4];
#pragma unroll
        for (int mi = 0; mi < 4; mi++)
#pragma unroll
            for (int ni = 0; ni < 8; ni++)
#pragma unroll
                for (int q = 0; q < 4; q++) acc[mi][ni][q] = 0.f;

#pragma unroll
        for (int ks = 0; ks < 8; ks++) {
            uint32_t coff = (uint32_t)((((ks << 1) | hi) ^ l7) << 4);
            uint32_t a[4][4];
#pragma unroll
            for (int mi = 0; mi < 4; mi++)
                ldsm_x4(a[mi], aAddr + mi * 16 * 256 + coff);
            uint32_t b[4][4];
#pragma unroll
            for (int nj = 0; nj < 4; nj++)
                ldsm_x4(b[nj], bRow + nj * 16 * 256 + coff);
#pragma unroll
            for (int nj = 0; nj < 4; nj++)
#pragma unroll
                for (int mi = 0; mi < 4; mi++) {
                    mma16816(acc[mi][nj * 2 + 0], a[mi], b[nj][0], b[nj][2]);
                    mma16816(acc[mi][nj * 2 + 1], a[mi], b[nj][1], b[nj][3]);
                }
        }

        // harvest positive logits: diagonal of the partner tile (raw dots)
        if (bj == posBj && warpM == warpN) {
#pragma unroll
            for (int mi = 0; mi < 4; mi++)
#pragma unroll
                for (int ni = 0; ni < 8; ni++) {
                    int r0 = woff + mi * 16 + g, r1 = r0 + 8;
                    int c0 = noff + ni * 8 + t * 2, c1 = c0 + 1;
                    if (r0 == c0) { posOutA[r0] = acc[mi][ni][0]; posOutB[r0] = acc[mi][ni][0]; }
                    if (r0 == c1) { posOutA[r0] = acc[mi][ni][1]; posOutB[r0] = acc[mi][ni][1]; }
                    if (r1 == c0) { posOutA[r1] = acc[mi][ni][2]; posOutB[r1] = acc[mi][ni][2]; }
                    if (r1 == c1) { posOutA[r1] = acc[mi][ni][3]; posOutB[r1] = acc[mi][ni][3]; }
                }
        }

        // epilogue: e = exp(10d) via f16x2 ex2 (fp32 args/accum)
        float rsum[4][2];
        float csum[16];
#pragma unroll
        for (int mi = 0; mi < 4; mi++) { rsum[mi][0] = 0.f; rsum[mi][1] = 0.f; }
#pragma unroll
        for (int k2 = 0; k2 < 16; k2++) csum[k2] = 0.f;

        if (diagW) {
#pragma unroll
            for (int mi = 0; mi < 4; mi++)
#pragma unroll
                for (int ni = 0; ni < 8; ni++) EPI_BLOCK(true);
        } else {
#pragma unroll
            for (int mi = 0; mi < 4; mi++)
#pragma unroll
                for (int ni = 0; ni < 8; ni++) EPI_BLOCK(false);
        }

        float* red = (float*)(sm + SM_RED + (i & 1) * 2048);
#pragma unroll
        for (int mi = 0; mi < 4; mi++)
#pragma unroll
            for (int h = 0; h < 2; h++) {
                float v = rsum[mi][h];
                v += __shfl_xor_sync(~0u, v, 1);
                v += __shfl_xor_sync(~0u, v, 2);
                if (t == 0) red[warpN * 128 + woff + mi * 16 + h * 8 + g] = v;
            }
#pragma unroll
        for (int k2 = 0; k2 < 16; k2++) {
            float v = csum[k2];
            v += __shfl_xor_sync(~0u, v, 4);
            v += __shfl_xor_sync(~0u, v, 8);
            v += __shfl_xor_sync(~0u, v, 16);
            if (g == 0) red[256 + warpM * 128 + noff + (k2 >> 1) * 8 + t * 2 + (k2 & 1)] = v;
        }

        outRprev = partBase + (size_t)(rowIdx * pairStrideRow + bj) * 128;
        outCprev = partBase + (size_t)(bj * pairStrideRow + rowIdx) * 128;
        diagprev = diag;
    }

    __syncthreads();
    {
        float* rr = (float*)(sm + SM_RED + ((L - 1) & 1) * 2048);
        outRprev[tid] = rr[tid] + rr[128 + tid];
        if (!diagprev) outCprev[tid] = rr[256 + tid] + rr[384 + tid];
    }
}

// ---------------------------------------------------------------------------
// Fused fixup + last-block combine. loss_r = log(S_r) - 10*pos_r.
// ---------------------------------------------------------------------------
__global__ void fin_all(const int* __restrict__ c1, const int* __restrict__ c2,
                        float* __restrict__ out) {
    __shared__ float S2a[8][32];
    __shared__ float S2b[256];
    __shared__ float S[128];
    __shared__ float rs[256];
    __shared__ int ri2[256];
    __shared__ int sLast;
    int tid = threadIdx.x;

    if (blockIdx.x < 512) {
        int bi = blockIdx.x >> 2, q = blockIdx.x & 3;
        int m = tid & 31, jg = tid >> 5;

        const float* base = g_part + (size_t)bi * 128 * 128 + q * 32 + m;
        float s = 0.0f;
#pragma unroll
        for (int j = jg * 16; j < jg * 16 + 16; j++) s += base[(size_t)j * 128];
        S2a[jg][m] = s;
        __syncthreads();
        if (tid < 32) {
            float v = 0.0f;
#pragma unroll
            for (int j = 0; j < 8; j++) v += S2a[j][tid];
            int r = bi * 128 + q * 32 + tid;
            float acc = logf(v) - 10.0f * g_posI[r];
#pragma unroll
            for (int o = 16; o; o >>= 1) acc += __shfl_xor_sync(~0u, acc, o);
            if (tid == 0) g_fin1[blockIdx.x] = acc;
        }
    } else {
        int pc = blockIdx.x - 512;
        int b = pc >> 2, bi = pc & 3;
        int m = tid & 127, jh = tid >> 7;

        const float* base = g_pp + ((size_t)b * 16 + bi * 4) * 128 + m;
        float s = 0.0f;
#pragma unroll
        for (int j = jh * 2; j < jh * 2 + 2; j++) s += base[(size_t)j * 128];
        S2b[tid] = s;
        __syncthreads();
        if (tid < 128) S[tid] = S2b[tid] + S2b[tid + 128];
        __syncthreads();

        float lv = 0.0f;
        int cnt = 0;
        if (tid < 128) {
            int rl = bi * 128 + tid;
            int r = b * 512 + rl;
            int c = (rl < 256) ? c1[b * 256 + rl] : c2[b * 256 + rl - 256];
            if (c != 0) {
                lv = logf(S[tid]) - 10.0f * g_posP[r];
                cnt = 1;
            }
        }
        rs[tid] = lv; ri2[tid] = cnt;
        __syncthreads();
        for (int s2 = 128; s2; s2 >>= 1) {
            if (tid < s2) { rs[tid] += rs[tid + s2]; ri2[tid] += ri2[tid + s2]; }
            __syncthreads();
        }
        if (tid == 0) { g_fin2[pc] = rs[0]; g_cnt2[pc] = ri2[0]; }
    }

    // ---- last block: final deterministic combine ----
    __threadfence();
    __syncthreads();
    if (tid == 0) {
        int ticket = atomicAdd(&g_done, 1);
        sLast = (ticket == 1535);
    }
    __syncthreads();
    if (!sLast) return;

    __shared__ float frs[256];
    __shared__ int fri[256];
    float a = g_fin1[tid] + g_fin1[tid + 256];
    float p = g_fin2[tid] + g_fin2[tid + 256] + g_fin2[tid + 512] + g_fin2[tid + 768];
    int cnt = g_cnt2[tid] + g_cnt2[tid + 256] + g_cnt2[tid + 512] + g_cnt2[tid + 768];
    frs[tid] = a; fri[tid] = cnt;
    __syncthreads();
    for (int s = 128; s; s >>= 1) {
        if (tid < s) { frs[tid] += frs[tid + s]; fri[tid] += fri[tid + s]; }
        __syncthreads();
    }
    float ins_sum = frs[0];
    int nvalid = fri[0];
    __syncthreads();
    frs[tid] = p;
    __syncthreads();
    for (int s = 128; s; s >>= 1) { if (tid < s) frs[tid] += frs[tid + s]; __syncthreads(); }
    if (tid == 0) {
        out[0] = ins_sum / (float)N_INS + frs[0] / (float)nvalid;
        g_done = 0;   // reset for next graph replay
    }
}

// ---------------------------------------------------------------------------
extern "C" void kernel_launch(void* const* d_in, const int* in_sizes, int n_in,
                              void* d_out, int out_size) {
    const float* v1  = (const float*)d_in[0];
    const float* v2  = (const float*)d_in[1];
    const float* v1p = (const float*)d_in[2];
    const float* v2p = (const float*)d_in[3];
    const int*   c1  = (const int*)d_in[4];
    const int*   c2  = (const int*)d_in[5];
    float* out = (float*)d_out;

    cudaFuncSetAttribute(k_main, cudaFuncAttributeMaxDynamicSharedMemorySize, SM_DYN);

    prep_all<<<2560, 256>>>(v1, v2, v1p, v2p);
    k_main<<<NI_CTAS + 1024, 128, SM_DYN>>>();
    fin_all<<<1536, 256>>>(c1, c2, out);
}